// round 14
// baseline (speedup 1.0000x reference)
#include <cuda_runtime.h>
#include <cuda_bf16.h>
#include <cuda_fp16.h>
#include <math.h>
#include <stdint.h>

#define Bn 16
#define Qn 128
#define Kn 4096
#define Dn 512
#define Hn 8
#define Cn 64
#define MQn 32
#define KEEPN 33   // MQ + 1

#define NELEM_QD ((size_t)Bn*Qn*Dn)
#define NELEM_KD ((size_t)Bn*Kn*Dn)
#define NELEM_ATT ((size_t)Bn*Hn*KEEPN*Kn)
#define NELEM_S1 ((size_t)Bn*Hn*KEEPN*Dn)
#define NELEM_PRE ((size_t)Bn*KEEPN*Dn)

// ---------------- scratch (device globals; no allocation allowed) ----------------
static __device__ __nv_bfloat16 g_qsum_h[NELEM_QD], g_qsum_l[NELEM_QD];
static __device__ __nv_bfloat16 g_ksum_h[NELEM_KD], g_ksum_l[NELEM_KD];
static __device__ __half        g_ctxT_h[NELEM_KD];                 // [B,D,K] fp16
static __device__ __half        g_ctxeT_h[NELEM_KD];                // [B,D,K] fp16
static __device__ __nv_bfloat16 g_wh[6*512*512], g_wl[6*512*512]; // Wq Wk Wf We Wof Woe
static __device__ __nv_bfloat16 g_qh[NELEM_QD], g_ql[NELEM_QD];
static __device__ __nv_bfloat16 g_kh[NELEM_KD], g_kl[NELEM_KD];
static __device__ __half       g_atf[NELEM_ATT];                 // attn [B,H,33,K], fp16
static __device__ __nv_bfloat16 g_s1nh[2][NELEM_S1], g_s1nl[2][NELEM_S1];
static __device__ __nv_bfloat16 g_preh[2][NELEM_PRE], g_prel[2][NELEM_PRE];
static __device__ float g_score[Bn*(Qn-1)];
static __device__ int   g_keep [Bn*KEEPN];
static __device__ float g_rowsum[Bn*Hn*KEEPN];

// ---------------- helpers ----------------
__device__ __forceinline__ uint32_t s2u(const void* p) {
    uint32_t r;
    asm("{ .reg .u64 t; cvta.to.shared.u64 t, %1; cvt.u32.u64 %0, t; }" : "=r"(r) : "l"(p));
    return r;
}
__device__ __forceinline__ void split1(float v, __nv_bfloat16& h, __nv_bfloat16& l) {
    h = __float2bfloat16(v);
    l = __float2bfloat16(v - __bfloat162float(h));
}
template<int F16>
__device__ __forceinline__ void mmaAB(float* d, const uint32_t* a, const uint32_t* b) {
    if (F16)
        asm volatile(
            "mma.sync.aligned.m16n8k16.row.col.f32.f16.f16.f32 "
            "{%0,%1,%2,%3}, {%4,%5,%6,%7}, {%8,%9}, {%0,%1,%2,%3};"
            : "+f"(d[0]), "+f"(d[1]), "+f"(d[2]), "+f"(d[3])
            : "r"(a[0]), "r"(a[1]), "r"(a[2]), "r"(a[3]), "r"(b[0]), "r"(b[1]));
    else
        asm volatile(
            "mma.sync.aligned.m16n8k16.row.col.f32.bf16.bf16.f32 "
            "{%0,%1,%2,%3}, {%4,%5,%6,%7}, {%8,%9}, {%0,%1,%2,%3};"
            : "+f"(d[0]), "+f"(d[1]), "+f"(d[2]), "+f"(d[3])
            : "r"(a[0]), "r"(a[1]), "r"(a[2]), "r"(a[3]), "r"(b[0]), "r"(b[1]));
}
__device__ __forceinline__ void ldsm4(uint32_t& r0, uint32_t& r1, uint32_t& r2, uint32_t& r3,
                                      uint32_t addr) {
    asm volatile("ldmatrix.sync.aligned.m8n8.x4.shared.b16 {%0,%1,%2,%3}, [%4];"
                 : "=r"(r0), "=r"(r1), "=r"(r2), "=r"(r3) : "r"(addr));
}

// ---------------- unified NT split GEMM ----------------
// PROD=3: bf16 3-term (AhBh + AlBh + AhBl). PROD=1: fp16 1-product.
// Pairing: z >= zpair -> switch (A*, B*, bias), offset C, nrows=nrowsPair.
// rowscale: row r scaled by 1/(rowscale[b*rsStride + r] + 1e-8).
// mode: 0 = fp32 out (+bias), 1 = split bf16 h/l out,
//       2 = SCORE ONLY (no C write; fused query-scoring into g_score).
#define BM 128
#define BN 128
#define BKt 16

template<int PROD>
__global__ void __launch_bounds__(256, 2) bs_gemm(
    const __nv_bfloat16* __restrict__ Ah, const __nv_bfloat16* __restrict__ Al,
    const __nv_bfloat16* __restrict__ Ahb, const __nv_bfloat16* __restrict__ Alb,
    int lda,
    const __nv_bfloat16* __restrict__ Bh, const __nv_bfloat16* __restrict__ Bl,
    const __nv_bfloat16* __restrict__ Bhb, const __nv_bfloat16* __restrict__ Blb,
    int ldb,
    const float* __restrict__ bias, const float* __restrict__ biasb,
    const float* __restrict__ rowscale, int rsStride,
    float* __restrict__ Cf, __nv_bfloat16* __restrict__ CH, __nv_bfloat16* __restrict__ CL,
    long long sCpair, long long sCpairL, int ldc,
    int nrows, int nrowsPair, int ncols, int kdim, float scale, int zdiv, int zpair,
    long long sAb, long long sAhh, long long sBb, long long sBhh,
    long long sCb, long long sChh, int mode)
{
    __shared__ __align__(16) uint4 sbuf[2][4][2][128];
    __shared__ float scoreBuf[BN + BM];

    int z = blockIdx.z;
    if (z >= zpair) {
        z -= zpair;
        if (Ahb) { Ah = Ahb; Al = Alb; }
        if (Bhb) { Bh = Bhb; Bl = Blb; }
        bias = biasb;
        if (Cf) Cf += sCpair;
        if (CH) { CH += sCpair; CL += sCpairL; }
        nrows = nrowsPair;
    }
    const int row0 = blockIdx.y * BM, col0 = blockIdx.x * BN;
    if (row0 >= nrows || col0 >= ncols) return;

    const int b = z / zdiv, h = z - b * zdiv;
    {
        long long ao = (long long)b * sAb + (long long)h * sAhh;
        long long bo = (long long)b * sBb + (long long)h * sBhh;
        long long co = (long long)b * sCb + (long long)h * sChh;
        Ah += ao; Al += ao;
        Bh += bo; Bl += bo;
        if (Cf) Cf += co;
        if (CH) { CH += co; CL += co; }
    }

    const int tid = threadIdx.x, lane = tid & 31, warp = tid >> 5;
    const int wr = warp >> 2, wc = warp & 3;
    const int g = lane >> 2, t = lane & 3;
    const int lr = tid >> 1, hf = tid & 1;   // loader row / k-half

    const int valid_m = nrows - row0;
    const int valid_n = ncols - col0;
    bool mAct[4], nAct[2];
    #pragma unroll
    for (int mi = 0; mi < 4; mi++) mAct[mi] = (wr * 64 + mi * 16) < valid_m;
    #pragma unroll
    for (int j = 0; j < 2; j++) nAct[j] = (wc * 32 + j * 16) < valid_n;

    float acc[4][4][4];
    #pragma unroll
    for (int mi = 0; mi < 4; mi++)
        #pragma unroll
        for (int ni = 0; ni < 4; ni++)
            #pragma unroll
            for (int j = 0; j < 4; j++) acc[mi][ni][j] = 0.f;

    uint4 rAh, rAl, rBh, rBl;
    const uint4 Z4 = make_uint4(0u, 0u, 0u, 0u);

    auto ld = [&](int k0) {
        long long ao = (long long)(row0 + lr) * lda + k0 + hf * 8;
        if (row0 + lr < nrows) {
            rAh = *(const uint4*)(Ah + ao);
            if (PROD == 3) rAl = *(const uint4*)(Al + ao);
        } else { rAh = Z4; rAl = Z4; }
        long long bo = (long long)(col0 + lr) * ldb + k0 + hf * 8;
        if (col0 + lr < ncols) {
            rBh = *(const uint4*)(Bh + bo);
        } else { rBh = Z4; }
        if (PROD == 3) {
            if (col0 + lr < ncols) rBl = *(const uint4*)(Bl + bo);
            else rBl = Z4;
        }
    };
    auto st = [&](int s) {
        sbuf[s][0][hf][lr] = rAh;
        if (PROD == 3) sbuf[s][1][hf][lr] = rAl;
        sbuf[s][2][hf][lr] = rBh;
        if (PROD == 3) sbuf[s][3][hf][lr] = rBl;
    };

    const uint32_t sb0 = s2u(&sbuf[0][0][0][0]);
    const int a_off = ((lane >> 4) & 1) * 2048 + (((lane >> 3) & 1) * 8 + (lane & 7)) * 16;
    const int bq = lane >> 3;
    const int b_off = (bq & 1) * 2048 + (wc * 32 + (bq >> 1) * 8 + (lane & 7)) * 16;

    auto step = [&](int s) {
        const uint32_t stg = sb0 + s * 16384;
        uint32_t bh4[4][2], bl4[4][2];
        #pragma unroll
        for (int j = 0; j < 2; j++) {
            if (!nAct[j]) continue;
            ldsm4(bh4[2*j][0], bh4[2*j][1], bh4[2*j+1][0], bh4[2*j+1][1],
                  stg + 2 * 4096 + b_off + j * 256);
            if (PROD == 3)
                ldsm4(bl4[2*j][0], bl4[2*j][1], bl4[2*j+1][0], bl4[2*j+1][1],
                      stg + 3 * 4096 + b_off + j * 256);
        }
        #pragma unroll
        for (int mi = 0; mi < 4; mi++) {
            if (!mAct[mi]) continue;
            const uint32_t rowb = (wr * 64 + mi * 16) * 16;
            uint32_t ah4[4], al4[4];
            ldsm4(ah4[0], ah4[1], ah4[2], ah4[3], stg + a_off + rowb);
            if (PROD == 3)
                ldsm4(al4[0], al4[1], al4[2], al4[3], stg + 4096 + a_off + rowb);
            #pragma unroll
            for (int ni = 0; ni < 4; ni++) {
                if (!nAct[ni >> 1]) continue;
                if (PROD == 3) {
                    mmaAB<0>(acc[mi][ni], ah4, bh4[ni]);
                    mmaAB<0>(acc[mi][ni], al4, bh4[ni]);
                    mmaAB<0>(acc[mi][ni], ah4, bl4[ni]);
                } else {
                    mmaAB<1>(acc[mi][ni], ah4, bh4[ni]);
                }
            }
        }
    };

    const int nt = kdim / BKt;
    ld(0); st(0);
    __syncthreads();
    for (int it = 0; it < nt; it++) {
        int cur = it & 1;
        if (it + 1 < nt) ld((it + 1) * BKt);
        step(cur);
        if (it + 1 < nt) { st(cur ^ 1); __syncthreads(); }
    }

    // ---- C epilogue (skipped in score-only mode)
    if (mode != 2) {
        #pragma unroll
        for (int mi = 0; mi < 4; mi++) {
            #pragma unroll
            for (int jj = 0; jj < 2; jj++) {
                int rr = row0 + wr * 64 + mi * 16 + g + jj * 8;
                if (rr >= nrows) continue;
                float rsc = scale;
                if (rowscale)
                    rsc = scale / (rowscale[(long long)b * rsStride + rr] + 1e-8f);
                #pragma unroll
                for (int ni = 0; ni < 4; ni++) {
                    int c = col0 + wc * 32 + ni * 8 + 2 * t;
                    if (c >= ncols) continue;
                    float v0 = acc[mi][ni][jj * 2 + 0] * rsc;
                    float v1 = acc[mi][ni][jj * 2 + 1] * rsc;
                    if (mode == 1) {
                        __nv_bfloat16 h0, l0, h1, l1;
                        split1(v0, h0, l0); split1(v1, h1, l1);
                        *(__nv_bfloat162*)(CH + (long long)rr * ldc + c) = __halves2bfloat162(h0, h1);
                        *(__nv_bfloat162*)(CL + (long long)rr * ldc + c) = __halves2bfloat162(l0, l1);
                    } else {
                        if (bias) { v0 += bias[c]; v1 += bias[c + 1]; }
                        *(float2*)(Cf + (long long)rr * ldc + c) = make_float2(v0, v1);
                    }
                }
            }
        }
    }

    // ---- fused query-scoring (score-only mode): exp stored back into acc
    if (mode == 2) {
        float* colsum = scoreBuf;
        float* rowmax = scoreBuf + BN;
        for (int i = tid; i < BN + BM; i += 256) scoreBuf[i] = 0.f;
        __syncthreads();

        float cs[8];
        #pragma unroll
        for (int q = 0; q < 8; q++) cs[q] = 0.f;
        #pragma unroll
        for (int mi = 0; mi < 4; mi++)
            #pragma unroll
            for (int ni = 0; ni < 4; ni++)
                #pragma unroll
                for (int j = 0; j < 4; j++) {
                    int grow = wr * 64 + mi * 16 + g + 8 * (j >> 1);
                    if (grow != 0) {
                        float e = __expf(acc[mi][ni][j] * scale);
                        acc[mi][ni][j] = e;
                        cs[ni * 2 + (j & 1)] += e;
                    }
                }
        #pragma unroll
        for (int o = 4; o <= 16; o <<= 1)
            #pragma unroll
            for (int q = 0; q < 8; q++)
                cs[q] += __shfl_xor_sync(0xffffffffu, cs[q], o);
        if (g == 0) {
            #pragma unroll
            for (int q = 0; q < 8; q++)
                atomicAdd(&colsum[wc * 32 + (q >> 1) * 8 + 2 * t + (q & 1)], cs[q]);
        }
        __syncthreads();

        float rm[8];
        #pragma unroll
        for (int q = 0; q < 8; q++) rm[q] = 0.f;
        #pragma unroll
        for (int mi = 0; mi < 4; mi++)
            #pragma unroll
            for (int ni = 0; ni < 4; ni++)
                #pragma unroll
                for (int j = 0; j < 4; j++) {
                    int grow = wr * 64 + mi * 16 + g + 8 * (j >> 1);
                    if (grow != 0) {
                        int c = wc * 32 + ni * 8 + 2 * t + (j & 1);
                        float v = acc[mi][ni][j] / colsum[c];
                        int qi = mi * 2 + (j >> 1);
                        rm[qi] = fmaxf(rm[qi], v);
                    }
                }
        #pragma unroll
        for (int o = 1; o <= 2; o <<= 1)
            #pragma unroll
            for (int q = 0; q < 8; q++)
                rm[q] = fmaxf(rm[q], __shfl_xor_sync(0xffffffffu, rm[q], o));
        if (t == 0) {
            #pragma unroll
            for (int q = 0; q < 8; q++)
                atomicMax((int*)&rowmax[wr * 64 + (q >> 1) * 16 + g + 8 * (q & 1)],
                          __float_as_int(rm[q]));
        }
        __syncthreads();
        if (tid >= 1 && tid < BM)
            atomicMax((int*)&g_score[b * (Qn - 1) + tid - 1],
                      __float_as_int(rowmax[tid]));
    }
}

// ---------------- fused gathered-dots + competitive softmax ----------------
// Grid (Kn/128, 1, Bn*Hn). A rows = the 33 kept queries of (b,h), gathered via
// g_keep. Computes dots (3-term bf16), softmax over the 33 queries per key
// (no max-shift; dots bounded), writes fp16 attn + per-row sums.
__global__ void __launch_bounds__(256, 2) attn_kernel() {
    __shared__ __align__(16) uint4 sbuf[2][4][2][128];
    __shared__ float colsum[BN];
    __shared__ int kq[KEEPN];

    const int z = blockIdx.z;
    const int b = z / Hn, h = z - b * Hn;
    const int col0 = blockIdx.x * BN;

    const int tid = threadIdx.x, lane = tid & 31, warp = tid >> 5;
    const int wr = warp >> 2, wc = warp & 3;
    const int g = lane >> 2, t = lane & 3;
    const int lr = tid >> 1, hf = tid & 1;

    if (tid < KEEPN) kq[tid] = g_keep[b * KEEPN + tid];
    for (int i = tid; i < BN; i += 256) colsum[i] = 0.f;
    __syncthreads();

    const __nv_bfloat16* Ah = g_qh + (long long)b * Qn * Dn + h * 64;
    const __nv_bfloat16* Al = g_ql + (long long)b * Qn * Dn + h * 64;
    const __nv_bfloat16* Bh = g_kh + (long long)b * Kn * Dn + h * 64;
    const __nv_bfloat16* Bl = g_kl + (long long)b * Kn * Dn + h * 64;

    float acc[3][4][4];   // wr==0 only uses mi 0..2 (rows 0..47; 33 valid)
    #pragma unroll
    for (int mi = 0; mi < 3; mi++)
        #pragma unroll
        for (int ni = 0; ni < 4; ni++)
            #pragma unroll
            for (int j = 0; j < 4; j++) acc[mi][ni][j] = 0.f;

    uint4 rAh, rAl, rBh, rBl;
    const uint4 Z4 = make_uint4(0u, 0u, 0u, 0u);
    auto ld = [&](int k0) {
        if (lr < KEEPN) {
            long long ao = (long long)kq[lr] * Dn + k0 + hf * 8;
            rAh = *(const uint4*)(Ah + ao);
            rAl = *(const uint4*)(Al + ao);
        } else { rAh = Z4; rAl = Z4; }
        long long bo = (long long)(col0 + lr) * Dn + k0 + hf * 8;
        rBh = *(const uint4*)(Bh + bo);
        rBl = *(const uint4*)(Bl + bo);
    };
    auto st = [&](int s) {
        sbuf[s][0][hf][lr] = rAh;
        sbuf[s][1][hf][lr] = rAl;
        sbuf[s][2][hf][lr] = rBh;
        sbuf[s][3][hf][lr] = rBl;
    };

    const uint32_t sb0 = s2u(&sbuf[0][0][0][0]);
    const int a_off = ((lane >> 4) & 1) * 2048 + (((lane >> 3) & 1) * 8 + (lane & 7)) * 16;
    const int bq = lane >> 3;
    const int b_off = (bq & 1) * 2048 + (wc * 32 + (bq >> 1) * 8 + (lane & 7)) * 16;

    auto step = [&](int s) {
        const uint32_t stg = sb0 + s * 16384;
        uint32_t bh4[4][2], bl4[4][2];
        #pragma unroll
        for (int j = 0; j < 2; j++) {
            ldsm4(bh4[2*j][0], bh4[2*j][1], bh4[2*j+1][0], bh4[2*j+1][1],
                  stg + 2 * 4096 + b_off + j * 256);
            ldsm4(bl4[2*j][0], bl4[2*j][1], bl4[2*j+1][0], bl4[2*j+1][1],
                  stg + 3 * 4096 + b_off + j * 256);
        }
        if (wr == 0) {
            #pragma unroll
            for (int mi = 0; mi < 3; mi++) {
                const uint32_t rowb = (mi * 16) * 16;
                uint32_t ah4[4], al4[4];
                ldsm4(ah4[0], ah4[1], ah4[2], ah4[3], stg + a_off + rowb);
                ldsm4(al4[0], al4[1], al4[2], al4[3], stg + 4096 + a_off + rowb);
                #pragma unroll
                for (int ni = 0; ni < 4; ni++) {
                    mmaAB<0>(acc[mi][ni], ah4, bh4[ni]);
                    mmaAB<0>(acc[mi][ni], al4, bh4[ni]);
                    mmaAB<0>(acc[mi][ni], ah4, bl4[ni]);
                }
            }
        }
    };

    const int nt = Cn / BKt;   // 4
    ld(0); st(0);
    __syncthreads();
    for (int it = 0; it < nt; it++) {
        int cur = it & 1;
        if (it + 1 < nt) ld((it + 1) * BKt);
        step(cur);
        if (it + 1 < nt) { st(cur ^ 1); __syncthreads(); }
    }

    // exp + column sums (rows < 33 only)
    if (wr == 0) {
        float cs[8];
        #pragma unroll
        for (int q = 0; q < 8; q++) cs[q] = 0.f;
        #pragma unroll
        for (int mi = 0; mi < 3; mi++)
            #pragma unroll
            for (int ni = 0; ni < 4; ni++)
                #pragma unroll
                for (int j = 0; j < 4; j++) {
                    int grow = mi * 16 + g + 8 * (j >> 1);
                    if (grow < KEEPN) {
                        float e = __expf(acc[mi][ni][j] * 0.125f);
                        acc[mi][ni][j] = e;
                        cs[ni * 2 + (j & 1)] += e;
                    }
                }
        #pragma unroll
        for (int o = 4; o <= 16; o <<= 1)
            #pragma unroll
            for (int q = 0; q < 8; q++)
                cs[q] += __shfl_xor_sync(0xffffffffu, cs[q], o);
        if (g == 0) {
            #pragma unroll
            for (int q = 0; q < 8; q++)
                atomicAdd(&colsum[wc * 32 + (q >> 1) * 8 + 2 * t + (q & 1)], cs[q]);
        }
    }
    __syncthreads();

    // attn = e / colsum; write fp16 + rowsum atomics
    if (wr == 0) {
        __half* outp = g_atf + ((long long)z * KEEPN) * Kn;
        #pragma unroll
        for (int mi = 0; mi < 3; mi++) {
            #pragma unroll
            for (int jj = 0; jj < 2; jj++) {
                int rr = mi * 16 + g + jj * 8;
                if (rr >= KEEPN) continue;
                float rowacc = 0.f;
                #pragma unroll
                for (int ni = 0; ni < 4; ni++) {
                    int cl = wc * 32 + ni * 8 + 2 * t;
                    float a0 = acc[mi][ni][jj * 2 + 0] / colsum[cl];
                    float a1 = acc[mi][ni][jj * 2 + 1] / colsum[cl + 1];
                    *(__half2*)(outp + (long long)rr * Kn + col0 + cl) =
                        __floats2half2_rn(a0, a1);
                    rowacc += a0 + a1;
                }
                rowacc += __shfl_xor_sync(0xffffffffu, rowacc, 1);
                rowacc += __shfl_xor_sync(0xffffffffu, rowacc, 2);
                if (t == 0)
                    atomicAdd(&g_rowsum[z * KEEPN + rr], rowacc);
            }
        }
    }
}

// ---------------- split / transpose ctx & ctx_enc ----------------
__global__ void split_ctx_kernel(const float* __restrict__ ctx, const float* __restrict__ ctxe) {
    __shared__ float tc_[32][33], te_[32][33];
    int bb = blockIdx.z, d0 = blockIdx.x * 32, k0 = blockIdx.y * 32;
    int tx = threadIdx.x, ty = threadIdx.y;
    const float* pc = ctx  + ((long long)bb * Kn + k0) * Dn + d0;
    const float* pe = ctxe + ((long long)bb * Kn + k0) * Dn + d0;
    #pragma unroll
    for (int j = 0; j < 4; j++) {
        int kk = ty + j * 8;
        float c = pc[(long long)kk * Dn + tx];
        float e = pe[(long long)kk * Dn + tx];
        tc_[kk][tx] = c; te_[kk][tx] = e;
        __nv_bfloat16 sh, sl;
        split1(c + e, sh, sl);
        long long o = ((long long)bb * Kn + k0 + kk) * Dn + d0 + tx;
        g_ksum_h[o] = sh; g_ksum_l[o] = sl;
    }
    __syncthreads();
    #pragma unroll
    for (int j = 0; j < 4; j++) {
        int dd = ty + j * 8;
        long long o = ((long long)bb * Dn + d0 + dd) * Kn + k0 + tx;
        g_ctxT_h[o]  = __float2half(tc_[tx][dd]);
        g_ctxeT_h[o] = __float2half(te_[tx][dd]);
    }
}

// ---------------- weight + qsum splits (7 jobs, one launch) ----------------
__global__ void split7_kernel(const float* __restrict__ w0, const float* __restrict__ w1,
                              const float* __restrict__ w2, const float* __restrict__ w3,
                              const float* __restrict__ w4, const float* __restrict__ w5,
                              const float* __restrict__ slots,
                              const float* __restrict__ slots_enc) {
    const int WN = 512 * 512;
    int job = blockIdx.y;
    int i = blockIdx.x * 256 + threadIdx.x;
    if (job < 6) {
        if (i >= WN) return;
        const float* src = (job == 0) ? w0 : (job == 1) ? w1 : (job == 2) ? w2
                         : (job == 3) ? w3 : (job == 4) ? w4 : w5;
        __nv_bfloat16 hh, ll;
        split1(src[i], hh, ll);
        g_wh[job * WN + i] = hh;
        g_wl[job * WN + i] = ll;
    } else {
        if (i >= (int)NELEM_QD) return;
        __nv_bfloat16 hh, ll;
        split1(slots[i] + slots_enc[i], hh, ll);
        g_qsum_h[i] = hh; g_qsum_l[i] = ll;
    }
}

// ---------------- per-launch state reset ----------------
__global__ void init_kernel() {
    for (int i = threadIdx.x; i < Bn*(Qn-1); i += 256) g_score[i] = 0.f;
    for (int i = threadIdx.x; i < Bn*Hn*KEEPN; i += 256) g_rowsum[i] = 0.f;
}

// ---------------- top-32 selection (ties -> lower index) ----------------
__global__ void topk_kernel() {
    int b = blockIdx.x;
    int t = threadIdx.x;   // 128
    __shared__ float sv[128];
    __shared__ float rv[128];
    __shared__ int   ri[128];
    sv[t] = (t < Qn-1) ? g_score[b*(Qn-1) + t] : -INFINITY;
    __syncthreads();
    for (int r = 0; r < MQn; r++) {
        rv[t] = sv[t]; ri[t] = t;
        __syncthreads();
        for (int off = 64; off > 0; off >>= 1) {
            if (t < off) {
                float v2 = rv[t+off]; int i2 = ri[t+off];
                if (v2 > rv[t] || (v2 == rv[t] && i2 < ri[t])) { rv[t] = v2; ri[t] = i2; }
            }
            __syncthreads();
        }
        int win = ri[0];
        if (t == 0) g_keep[b*KEEPN + 1 + r] = win + 1;
        if (t == win) sv[t] = -INFINITY;
        __syncthreads();
    }
    if (t == 0) g_keep[b*KEEPN] = 0;
}

__global__ void finalize_keep_kernel(float* outp) {
    int i = blockIdx.x * 256 + threadIdx.x;
    if (i < Bn*KEEPN) outp[i] = (float)g_keep[i];
}

// ---------------- launch ----------------
extern "C" void kernel_launch(void* const* d_in, const int* in_sizes, int n_in,
                              void* d_out, int out_size) {
    const float* slots     = (const float*)d_in[0];
    const float* slots_enc = (const float*)d_in[1];
    const float* ctx       = (const float*)d_in[2];
    const float* ctx_enc   = (const float*)d_in[3];
    const float* Wq  = (const float*)d_in[4];
    const float* Wk  = (const float*)d_in[5];
    const float* Wf  = (const float*)d_in[6];
    const float* We  = (const float*)d_in[7];
    const float* Wof = (const float*)d_in[8];
    const float* bof = (const float*)d_in[9];
    const float* Woe = (const float*)d_in[10];
    const float* boe = (const float*)d_in[11];
    float* outp = (float*)d_out;

    __nv_bfloat16 *pqsh, *pqsl, *pksh, *pksl;
    __half *pcth, *pceh, *patf;
    __nv_bfloat16 *pwh, *pwl, *pqh, *pql, *pkh, *pkl;
    __nv_bfloat16 *ps1nh, *ps1nl, *ppreh, *pprel;
    float *prowsum;
    cudaGetSymbolAddress((void**)&pqsh, g_qsum_h);  cudaGetSymbolAddress((void**)&pqsl, g_qsum_l);
    cudaGetSymbolAddress((void**)&pksh, g_ksum_h);  cudaGetSymbolAddress((void**)&pksl, g_ksum_l);
    cudaGetSymbolAddress((void**)&pcth, g_ctxT_h);
    cudaGetSymbolAddress((void**)&pceh, g_ctxeT_h);
    cudaGetSymbolAddress((void**)&pwh, g_wh);       cudaGetSymbolAddress((void**)&pwl, g_wl);
    cudaGetSymbolAddress((void**)&pqh, g_qh);       cudaGetSymbolAddress((void**)&pql, g_ql);
    cudaGetSymbolAddress((void**)&pkh, g_kh);       cudaGetSymbolAddress((void**)&pkl, g_kl);
    cudaGetSymbolAddress((void**)&patf, g_atf);
    cudaGetSymbolAddress((void**)&ps1nh, g_s1nh);   cudaGetSymbolAddress((void**)&ps1nl, g_s1nl);
    cudaGetSymbolAddress((void**)&ppreh, g_preh);   cudaGetSymbolAddress((void**)&pprel, g_prel);
    cudaGetSymbolAddress((void**)&prowsum, g_rowsum);

    const int ZBIG = 1 << 30;
    const int WN = 512 * 512;
    dim3 T(256);

    split_ctx_kernel<<<dim3(Dn/32, Kn/32, Bn), dim3(32, 8)>>>(ctx, ctx_enc);
    split7_kernel<<<dim3((int)((NELEM_QD + 255)/256), 7), T>>>(Wq, Wk, Wf, We, Wof, Woe,
                                                               slots, slots_enc);
    init_kernel<<<1, 256>>>();

    // merged k-proj (z=0) + q-proj (z=1, nrowsPair=2048, extra y-tiles exit early)
    bs_gemm<3><<<dim3(4, 512, 2), T>>>(pksh, pksl, pqsh, pqsl, Dn,
        pwh + 1*WN, pwl + 1*WN, pwh + 0*WN, pwl + 0*WN, Dn,
        nullptr, nullptr, nullptr, 0,
        nullptr, pkh, pkl, (long long)(pqh - pkh), (long long)(pql - pkl), Dn,
        Bn*Kn, Bn*Qn, Dn, Dn, 1.f, 1, 1,
        0, 0, 0, 0, 0, 0, 1);

    // dots SCORE pass: [128 x 4096 x 64] batched (b,h), no C write
    bs_gemm<3><<<dim3(Kn/128, 1, Bn*Hn), T>>>(pqh, pql, nullptr, nullptr, Dn,
        pkh, pkl, nullptr, nullptr, Dn,
        nullptr, nullptr, nullptr, 0,
        nullptr, nullptr, nullptr, 0, 0, Kn,
        Qn, Qn, Kn, Cn, 0.125f, Hn, ZBIG,
        (long long)Qn*Dn, 64, (long long)Kn*Dn, 64,
        0, 0, 2);

    topk_kernel<<<Bn, 128>>>();

    // fused gathered dots + competitive softmax -> g_atf, g_rowsum
    attn_kernel<<<dim3(Kn/128, 1, Bn*Hn), T>>>();

    // AV paired (fp16 1-product) + fused key-renorm + split out: [264 x 512 x 4096] batched b
    bs_gemm<1><<<dim3(4, 3, 2*Bn), T>>>(
        (const __nv_bfloat16*)patf, nullptr, nullptr, nullptr, Kn,
        (const __nv_bfloat16*)pcth, nullptr,
        (const __nv_bfloat16*)pceh, nullptr, Kn,
        nullptr, nullptr, prowsum, Hn*KEEPN,
        nullptr, ps1nh, ps1nl, (long long)NELEM_S1, (long long)NELEM_S1, Dn,
        Hn*KEEPN, Hn*KEEPN, Dn, Kn, 1.f, 1, Bn,
        (long long)Hn*KEEPN*Kn, 0, (long long)Dn*Kn, 0,
        (long long)Hn*KEEPN*Dn, 0, 1);

    // per-head contraction paired: [33 x 64 x 512] batched (b,h), split out
    bs_gemm<3><<<dim3(1, 1, 2*Bn*Hn), T>>>(ps1nh, ps1nl, ps1nh + NELEM_S1, ps1nl + NELEM_S1, Dn,
        pwh + 2*WN, pwl + 2*WN, pwh + 3*WN, pwl + 3*WN, Dn,
        nullptr, nullptr, nullptr, 0,
        nullptr, ppreh, pprel, (long long)NELEM_PRE, (long long)NELEM_PRE, Dn,
        KEEPN, KEEPN, Cn, Dn, 1.f, Hn, Bn*Hn,
        (long long)Hn*KEEPN*Dn, (long long)KEEPN*Dn,
        0, (long long)Cn*Dn,
        (long long)KEEPN*Dn, (long long)Cn, 1);

    // out-proj paired: [528 x 512 x 512] -> d_out
    bs_gemm<3><<<dim3(4, 5, 2), T>>>(ppreh, pprel, ppreh + NELEM_PRE, pprel + NELEM_PRE, Dn,
        pwh + 4*WN, pwl + 4*WN, pwh + 5*WN, pwl + 5*WN, Dn,
        bof, boe, nullptr, 0,
        outp, nullptr, nullptr, (long long)Bn*KEEPN*Dn, 0, Dn,
        Bn*KEEPN, Bn*KEEPN, Dn, Dn, 1.f, 1, 1,
        0, 0, 0, 0, 0, 0, 0);

    finalize_keep_kernel<<<3, 256>>>(outp + 2*(size_t)Bn*KEEPN*Dn);
}

// round 15
// speedup vs baseline: 1.0457x; 1.0457x over previous
#include <cuda_runtime.h>
#include <cuda_bf16.h>
#include <cuda_fp16.h>
#include <math.h>
#include <stdint.h>

#define Bn 16
#define Qn 128
#define Kn 4096
#define Dn 512
#define Hn 8
#define Cn 64
#define MQn 32
#define KEEPN 33   // MQ + 1

#define NELEM_QD ((size_t)Bn*Qn*Dn)
#define NELEM_KD ((size_t)Bn*Kn*Dn)
#define NELEM_DOTS ((size_t)Bn*Hn*Qn*Kn)
#define NELEM_ATT ((size_t)Bn*Hn*KEEPN*Kn)
#define NELEM_S1 ((size_t)Bn*Hn*KEEPN*Dn)
#define NELEM_PRE ((size_t)Bn*KEEPN*Dn)

// ---------------- scratch (device globals; no allocation allowed) ----------------
static __device__ __nv_bfloat16 g_qsum_h[NELEM_QD], g_qsum_l[NELEM_QD];
static __device__ __nv_bfloat16 g_ksum_h[NELEM_KD], g_ksum_l[NELEM_KD];
static __device__ __half        g_ctxT_h[NELEM_KD];                 // [B,D,K] fp16
static __device__ __half        g_ctxeT_h[NELEM_KD];                // [B,D,K] fp16
static __device__ __nv_bfloat16 g_wh[6*512*512], g_wl[6*512*512]; // Wq Wk Wf We Wof Woe
static __device__ __nv_bfloat16 g_qh[NELEM_QD], g_ql[NELEM_QD];
static __device__ __nv_bfloat16 g_kh[NELEM_KD], g_kl[NELEM_KD];
static __device__ float        g_dots[NELEM_DOTS];
static __device__ __half       g_atf[NELEM_ATT];                 // attn, single fp16 plane
static __device__ __nv_bfloat16 g_s1nh[2][NELEM_S1], g_s1nl[2][NELEM_S1];
static __device__ __nv_bfloat16 g_preh[2][NELEM_PRE], g_prel[2][NELEM_PRE];
static __device__ float g_score[Bn*(Qn-1)];
static __device__ int   g_keep [Bn*KEEPN];
static __device__ float g_rowsum[Bn*Hn*KEEPN];

// ---------------- helpers ----------------
__device__ __forceinline__ uint32_t s2u(const void* p) {
    uint32_t r;
    asm("{ .reg .u64 t; cvta.to.shared.u64 t, %1; cvt.u32.u64 %0, t; }" : "=r"(r) : "l"(p));
    return r;
}
__device__ __forceinline__ void split1(float v, __nv_bfloat16& h, __nv_bfloat16& l) {
    h = __float2bfloat16(v);
    l = __float2bfloat16(v - __bfloat162float(h));
}
template<int F16>
__device__ __forceinline__ void mmaAB(float* d, const uint32_t* a, const uint32_t* b) {
    if (F16)
        asm volatile(
            "mma.sync.aligned.m16n8k16.row.col.f32.f16.f16.f32 "
            "{%0,%1,%2,%3}, {%4,%5,%6,%7}, {%8,%9}, {%0,%1,%2,%3};"
            : "+f"(d[0]), "+f"(d[1]), "+f"(d[2]), "+f"(d[3])
            : "r"(a[0]), "r"(a[1]), "r"(a[2]), "r"(a[3]), "r"(b[0]), "r"(b[1]));
    else
        asm volatile(
            "mma.sync.aligned.m16n8k16.row.col.f32.bf16.bf16.f32 "
            "{%0,%1,%2,%3}, {%4,%5,%6,%7}, {%8,%9}, {%0,%1,%2,%3};"
            : "+f"(d[0]), "+f"(d[1]), "+f"(d[2]), "+f"(d[3])
            : "r"(a[0]), "r"(a[1]), "r"(a[2]), "r"(a[3]), "r"(b[0]), "r"(b[1]));
}
__device__ __forceinline__ void ldsm4(uint32_t& r0, uint32_t& r1, uint32_t& r2, uint32_t& r3,
                                      uint32_t addr) {
    asm volatile("ldmatrix.sync.aligned.m8n8.x4.shared.b16 {%0,%1,%2,%3}, [%4];"
                 : "=r"(r0), "=r"(r1), "=r"(r2), "=r"(r3) : "r"(addr));
}

// ---------------- unified NT split GEMM ----------------
// PROD=3: bf16 3-term (AhBh + AlBh + AhBl). PROD=1: fp16 1-product.
// GUARD=0: all tiles full (no bounds checks in mainloop).
// Pairing: z >= zpair -> switch (A*, B*, bias), offset C, nrows=nrowsPair.
// rowscale: row r scaled by 1/(rowscale[b*rsStride + r] + 1e-8).
// mode: 0 = fp32 out (+bias), 1 = split bf16 h/l out, 2 = fp32 out + fused scoring.
#define BM 128
#define BN 128
#define BKt 16

template<int PROD, int GUARD>
__global__ void __launch_bounds__(256, 2) bs_gemm(
    const __nv_bfloat16* __restrict__ Ah, const __nv_bfloat16* __restrict__ Al,
    const __nv_bfloat16* __restrict__ Ahb, const __nv_bfloat16* __restrict__ Alb,
    int lda,
    const __nv_bfloat16* __restrict__ Bh, const __nv_bfloat16* __restrict__ Bl,
    const __nv_bfloat16* __restrict__ Bhb, const __nv_bfloat16* __restrict__ Blb,
    int ldb,
    const float* __restrict__ bias, const float* __restrict__ biasb,
    const float* __restrict__ rowscale, int rsStride,
    float* __restrict__ Cf, __nv_bfloat16* __restrict__ CH, __nv_bfloat16* __restrict__ CL,
    long long sCpair, long long sCpairL, int ldc,
    int nrows, int nrowsPair, int ncols, int kdim, float scale, int zdiv, int zpair,
    long long sAb, long long sAhh, long long sBb, long long sBhh,
    long long sCb, long long sChh, int mode)
{
    __shared__ __align__(16) uint4 sbuf[2][4][2][128];
    __shared__ float scoreBuf[BN + BM];

    int z = blockIdx.z;
    if (z >= zpair) {
        z -= zpair;
        if (Ahb) { Ah = Ahb; Al = Alb; }
        if (Bhb) { Bh = Bhb; Bl = Blb; }
        bias = biasb;
        if (Cf) Cf += sCpair;
        if (CH) { CH += sCpair; CL += sCpairL; }
        nrows = nrowsPair;
    }
    const int row0 = blockIdx.y * BM, col0 = blockIdx.x * BN;
    if (row0 >= nrows || col0 >= ncols) return;

    const int b = z / zdiv, h = z - b * zdiv;
    {
        long long ao = (long long)b * sAb + (long long)h * sAhh;
        long long bo = (long long)b * sBb + (long long)h * sBhh;
        long long co = (long long)b * sCb + (long long)h * sChh;
        Ah += ao; Al += ao;
        Bh += bo; Bl += bo;
        if (Cf) Cf += co;
        if (CH) { CH += co; CL += co; }
    }

    const int tid = threadIdx.x, lane = tid & 31, warp = tid >> 5;
    const int wr = warp >> 2, wc = warp & 3;
    const int g = lane >> 2, t = lane & 3;
    const int lr = tid >> 1, hf = tid & 1;   // loader row / k-half

    const int valid_m = nrows - row0;
    const int valid_n = ncols - col0;
    bool mAct[4], nAct[2];
    #pragma unroll
    for (int mi = 0; mi < 4; mi++) mAct[mi] = !GUARD || (wr * 64 + mi * 16) < valid_m;
    #pragma unroll
    for (int j = 0; j < 2; j++) nAct[j] = !GUARD || (wc * 32 + j * 16) < valid_n;

    float acc[4][4][4];
    #pragma unroll
    for (int mi = 0; mi < 4; mi++)
        #pragma unroll
        for (int ni = 0; ni < 4; ni++)
            #pragma unroll
            for (int j = 0; j < 4; j++) acc[mi][ni][j] = 0.f;

    uint4 rAh, rAl, rBh, rBl;
    const uint4 Z4 = make_uint4(0u, 0u, 0u, 0u);

    // pointer-increment loaders (row*ld computed ONCE)
    const bool aValid = !GUARD || (row0 + lr < nrows);
    const bool bValid = !GUARD || (col0 + lr < ncols);
    const __nv_bfloat16 *pAh, *pAl = nullptr, *pBh, *pBl = nullptr;
    {
        long long ar = (long long)(aValid ? row0 + lr : 0) * lda + hf * 8;
        long long br = (long long)(bValid ? col0 + lr : 0) * ldb + hf * 8;
        pAh = Ah + ar;
        if (PROD == 3) pAl = Al + ar;
        pBh = Bh + br;
        if (PROD == 3) pBl = Bl + br;
    }
    auto ld = [&]() {
        if (aValid) {
            rAh = *(const uint4*)pAh;
            if (PROD == 3) rAl = *(const uint4*)pAl;
        } else { rAh = Z4; rAl = Z4; }
        if (bValid) {
            rBh = *(const uint4*)pBh;
            if (PROD == 3) rBl = *(const uint4*)pBl;
        } else { rBh = Z4; rBl = Z4; }
        pAh += BKt; pBh += BKt;
        if (PROD == 3) { pAl += BKt; pBl += BKt; }
    };
    auto st = [&](int s) {
        sbuf[s][0][hf][lr] = rAh;
        if (PROD == 3) sbuf[s][1][hf][lr] = rAl;
        sbuf[s][2][hf][lr] = rBh;
        if (PROD == 3) sbuf[s][3][hf][lr] = rBl;
    };

    const uint32_t sb0 = s2u(&sbuf[0][0][0][0]);
    const int a_off = ((lane >> 4) & 1) * 2048 + (((lane >> 3) & 1) * 8 + (lane & 7)) * 16;
    const int bq = lane >> 3;
    const int b_off = (bq & 1) * 2048 + (wc * 32 + (bq >> 1) * 8 + (lane & 7)) * 16;

    auto step = [&](int s) {
        const uint32_t stg = sb0 + s * 16384;
        uint32_t bh4[4][2], bl4[4][2];
        #pragma unroll
        for (int j = 0; j < 2; j++) {
            if (GUARD && !nAct[j]) continue;
            ldsm4(bh4[2*j][0], bh4[2*j][1], bh4[2*j+1][0], bh4[2*j+1][1],
                  stg + 2 * 4096 + b_off + j * 256);
            if (PROD == 3)
                ldsm4(bl4[2*j][0], bl4[2*j][1], bl4[2*j+1][0], bl4[2*j+1][1],
                      stg + 3 * 4096 + b_off + j * 256);
        }
        #pragma unroll
        for (int mi = 0; mi < 4; mi++) {
            if (GUARD && !mAct[mi]) continue;
            const uint32_t rowb = (wr * 64 + mi * 16) * 16;
            uint32_t ah4[4], al4[4];
            ldsm4(ah4[0], ah4[1], ah4[2], ah4[3], stg + a_off + rowb);
            if (PROD == 3)
                ldsm4(al4[0], al4[1], al4[2], al4[3], stg + 4096 + a_off + rowb);
            #pragma unroll
            for (int ni = 0; ni < 4; ni++) {
                if (GUARD && !nAct[ni >> 1]) continue;
                if (PROD == 3) {
                    mmaAB<0>(acc[mi][ni], ah4, bh4[ni]);
                    mmaAB<0>(acc[mi][ni], al4, bh4[ni]);
                    mmaAB<0>(acc[mi][ni], ah4, bl4[ni]);
                } else {
                    mmaAB<1>(acc[mi][ni], ah4, bh4[ni]);
                }
            }
        }
    };

    const int nt = kdim / BKt;
    ld(); st(0);
    __syncthreads();
    for (int it = 0; it < nt; it++) {
        int cur = it & 1;
        if (it + 1 < nt) ld();
        step(cur);
        if (it + 1 < nt) { st(cur ^ 1); __syncthreads(); }
    }

    // ---- epilogue (rows outer so per-row rowscale is hoisted)
    #pragma unroll
    for (int mi = 0; mi < 4; mi++) {
        #pragma unroll
        for (int jj = 0; jj < 2; jj++) {
            int rr = row0 + wr * 64 + mi * 16 + g + jj * 8;
            if (rr >= nrows) continue;
            float rsc = scale;
            if (rowscale)
                rsc = scale / (rowscale[(long long)b * rsStride + rr] + 1e-8f);
            #pragma unroll
            for (int ni = 0; ni < 4; ni++) {
                int c = col0 + wc * 32 + ni * 8 + 2 * t;
                if (c >= ncols) continue;
                float v0 = acc[mi][ni][jj * 2 + 0] * rsc;
                float v1 = acc[mi][ni][jj * 2 + 1] * rsc;
                if (mode == 1) {
                    __nv_bfloat16 h0, l0, h1, l1;
                    split1(v0, h0, l0); split1(v1, h1, l1);
                    *(__nv_bfloat162*)(CH + (long long)rr * ldc + c) = __halves2bfloat162(h0, h1);
                    *(__nv_bfloat162*)(CL + (long long)rr * ldc + c) = __halves2bfloat162(l0, l1);
                } else {
                    if (bias) { v0 += bias[c]; v1 += bias[c + 1]; }
                    *(float2*)(Cf + (long long)rr * ldc + c) = make_float2(v0, v1);
                }
            }
        }
    }

    // ---- fused query-scoring epilogue (dots only)
    if (mode == 2) {
        float* colsum = scoreBuf;
        float* rowmax = scoreBuf + BN;
        for (int i = tid; i < BN + BM; i += 256) scoreBuf[i] = 0.f;
        __syncthreads();

        float cs[8];
        #pragma unroll
        for (int q = 0; q < 8; q++) cs[q] = 0.f;
        #pragma unroll
        for (int mi = 0; mi < 4; mi++)
            #pragma unroll
            for (int ni = 0; ni < 4; ni++)
                #pragma unroll
                for (int j = 0; j < 4; j++) {
                    int grow = wr * 64 + mi * 16 + g + 8 * (j >> 1);
                    if (grow != 0)
                        cs[ni * 2 + (j & 1)] += __expf(acc[mi][ni][j] * scale);
                }
        #pragma unroll
        for (int o = 4; o <= 16; o <<= 1)
            #pragma unroll
            for (int q = 0; q < 8; q++)
                cs[q] += __shfl_xor_sync(0xffffffffu, cs[q], o);
        if (g == 0) {
            #pragma unroll
            for (int q = 0; q < 8; q++)
                atomicAdd(&colsum[wc * 32 + (q >> 1) * 8 + 2 * t + (q & 1)], cs[q]);
        }
        __syncthreads();

        float rm[8];
        #pragma unroll
        for (int q = 0; q < 8; q++) rm[q] = 0.f;
        #pragma unroll
        for (int mi = 0; mi < 4; mi++)
            #pragma unroll
            for (int ni = 0; ni < 4; ni++)
                #pragma unroll
                for (int j = 0; j < 4; j++) {
                    int grow = wr * 64 + mi * 16 + g + 8 * (j >> 1);
                    if (grow != 0) {
                        int c = wc * 32 + ni * 8 + 2 * t + (j & 1);
                        float v = __expf(acc[mi][ni][j] * scale) / colsum[c];
                        int qi = mi * 2 + (j >> 1);
                        rm[qi] = fmaxf(rm[qi], v);
                    }
                }
        #pragma unroll
        for (int o = 1; o <= 2; o <<= 1)
            #pragma unroll
            for (int q = 0; q < 8; q++)
                rm[q] = fmaxf(rm[q], __shfl_xor_sync(0xffffffffu, rm[q], o));
        if (t == 0) {
            #pragma unroll
            for (int q = 0; q < 8; q++)
                atomicMax((int*)&rowmax[wr * 64 + (q >> 1) * 16 + g + 8 * (q & 1)],
                          __float_as_int(rm[q]));
        }
        __syncthreads();
        if (tid >= 1 && tid < BM)
            atomicMax((int*)&g_score[b * (Qn - 1) + tid - 1],
                      __float_as_int(rowmax[tid]));
    }
}

// ---------------- split / transpose ctx & ctx_enc ----------------
__global__ void split_ctx_kernel(const float* __restrict__ ctx, const float* __restrict__ ctxe) {
    __shared__ float tc_[32][33], te_[32][33];
    int bb = blockIdx.z, d0 = blockIdx.x * 32, k0 = blockIdx.y * 32;
    int tx = threadIdx.x, ty = threadIdx.y;
    const float* pc = ctx  + ((long long)bb * Kn + k0) * Dn + d0;
    const float* pe = ctxe + ((long long)bb * Kn + k0) * Dn + d0;
    #pragma unroll
    for (int j = 0; j < 4; j++) {
        int kk = ty + j * 8;
        float c = pc[(long long)kk * Dn + tx];
        float e = pe[(long long)kk * Dn + tx];
        tc_[kk][tx] = c; te_[kk][tx] = e;
        __nv_bfloat16 sh, sl;
        split1(c + e, sh, sl);
        long long o = ((long long)bb * Kn + k0 + kk) * Dn + d0 + tx;
        g_ksum_h[o] = sh; g_ksum_l[o] = sl;
    }
    __syncthreads();
    #pragma unroll
    for (int j = 0; j < 4; j++) {
        int dd = ty + j * 8;
        long long o = ((long long)bb * Dn + d0 + dd) * Kn + k0 + tx;
        g_ctxT_h[o]  = __float2half(tc_[tx][dd]);
        g_ctxeT_h[o] = __float2half(te_[tx][dd]);
    }
}

// ---------------- weight + qsum splits (7 jobs, one launch) ----------------
__global__ void split7_kernel(const float* __restrict__ w0, const float* __restrict__ w1,
                              const float* __restrict__ w2, const float* __restrict__ w3,
                              const float* __restrict__ w4, const float* __restrict__ w5,
                              const float* __restrict__ slots,
                              const float* __restrict__ slots_enc) {
    const int WN = 512 * 512;
    int job = blockIdx.y;
    int i = blockIdx.x * 256 + threadIdx.x;
    if (job < 6) {
        if (i >= WN) return;
        const float* src = (job == 0) ? w0 : (job == 1) ? w1 : (job == 2) ? w2
                         : (job == 3) ? w3 : (job == 4) ? w4 : w5;
        __nv_bfloat16 hh, ll;
        split1(src[i], hh, ll);
        g_wh[job * WN + i] = hh;
        g_wl[job * WN + i] = ll;
    } else {
        if (i >= (int)NELEM_QD) return;
        __nv_bfloat16 hh, ll;
        split1(slots[i] + slots_enc[i], hh, ll);
        g_qsum_h[i] = hh; g_qsum_l[i] = ll;
    }
}

// ---------------- per-launch state reset ----------------
__global__ void init_kernel() {
    for (int i = threadIdx.x; i < Bn*(Qn-1); i += 256) g_score[i] = 0.f;
    for (int i = threadIdx.x; i < Bn*Hn*KEEPN; i += 256) g_rowsum[i] = 0.f;
}

// ---------------- top-32 selection (ties -> lower index) ----------------
__global__ void topk_kernel() {
    int b = blockIdx.x;
    int t = threadIdx.x;   // 128
    __shared__ float sv[128];
    __shared__ float rv[128];
    __shared__ int   ri[128];
    sv[t] = (t < Qn-1) ? g_score[b*(Qn-1) + t] : -INFINITY;
    __syncthreads();
    for (int r = 0; r < MQn; r++) {
        rv[t] = sv[t]; ri[t] = t;
        __syncthreads();
        for (int off = 64; off > 0; off >>= 1) {
            if (t < off) {
                float v2 = rv[t+off]; int i2 = ri[t+off];
                if (v2 > rv[t] || (v2 == rv[t] && i2 < ri[t])) { rv[t] = v2; ri[t] = i2; }
            }
            __syncthreads();
        }
        int win = ri[0];
        if (t == 0) g_keep[b*KEEPN + 1 + r] = win + 1;
        if (t == win) sv[t] = -INFINITY;
        __syncthreads();
    }
    if (t == 0) g_keep[b*KEEPN] = 0;
}

// ---------------- gather + competitive softmax (query axis), fp16 attn + rowsums ----------------
__global__ void softmax_kernel() {
    int b = blockIdx.z, h = blockIdx.y;
    int k = blockIdx.x * 128 + threadIdx.x;
    __shared__ int   kq[KEEPN];
    __shared__ float rs[KEEPN];
    if (threadIdx.x < KEEPN) {
        kq[threadIdx.x] = g_keep[b*KEEPN + threadIdx.x];
        rs[threadIdx.x] = 0.f;
    }
    __syncthreads();
    const float* base = g_dots + ((size_t)((b*Hn + h) * Qn)) * Kn + k;
    float d[KEEPN];
    float m = -INFINITY;
    #pragma unroll
    for (int j = 0; j < KEEPN; j++) {
        d[j] = base[(size_t)kq[j] * Kn];
        m = fmaxf(m, d[j]);
    }
    float s = 0.f;
    #pragma unroll
    for (int j = 0; j < KEEPN; j++) { d[j] = __expf(d[j] - m); s += d[j]; }
    float inv = 1.f / s;
    size_t obase = ((size_t)((b*Hn + h) * KEEPN)) * Kn + k;
    int lane = threadIdx.x & 31;
    #pragma unroll
    for (int j = 0; j < KEEPN; j++) {
        float a = d[j] * inv;
        g_atf[obase + (size_t)j * Kn] = __float2half(a);
        float w = a;
        #pragma unroll
        for (int o = 16; o > 0; o >>= 1) w += __shfl_xor_sync(0xffffffffu, w, o);
        if (lane == 0) atomicAdd(&rs[j], w);
    }
    __syncthreads();
    if (threadIdx.x < KEEPN)
        atomicAdd(&g_rowsum[(b*Hn + h)*KEEPN + threadIdx.x], rs[threadIdx.x]);
}

__global__ void finalize_keep_kernel(float* outp) {
    int i = blockIdx.x * 256 + threadIdx.x;
    if (i < Bn*KEEPN) outp[i] = (float)g_keep[i];
}

// ---------------- launch ----------------
extern "C" void kernel_launch(void* const* d_in, const int* in_sizes, int n_in,
                              void* d_out, int out_size) {
    const float* slots     = (const float*)d_in[0];
    const float* slots_enc = (const float*)d_in[1];
    const float* ctx       = (const float*)d_in[2];
    const float* ctx_enc   = (const float*)d_in[3];
    const float* Wq  = (const float*)d_in[4];
    const float* Wk  = (const float*)d_in[5];
    const float* Wf  = (const float*)d_in[6];
    const float* We  = (const float*)d_in[7];
    const float* Wof = (const float*)d_in[8];
    const float* bof = (const float*)d_in[9];
    const float* Woe = (const float*)d_in[10];
    const float* boe = (const float*)d_in[11];
    float* outp = (float*)d_out;

    __nv_bfloat16 *pqsh, *pqsl, *pksh, *pksl;
    __half *pcth, *pceh, *patf;
    __nv_bfloat16 *pwh, *pwl, *pqh, *pql, *pkh, *pkl;
    __nv_bfloat16 *ps1nh, *ps1nl, *ppreh, *pprel;
    float *pdots, *prowsum;
    cudaGetSymbolAddress((void**)&pqsh, g_qsum_h);  cudaGetSymbolAddress((void**)&pqsl, g_qsum_l);
    cudaGetSymbolAddress((void**)&pksh, g_ksum_h);  cudaGetSymbolAddress((void**)&pksl, g_ksum_l);
    cudaGetSymbolAddress((void**)&pcth, g_ctxT_h);
    cudaGetSymbolAddress((void**)&pceh, g_ctxeT_h);
    cudaGetSymbolAddress((void**)&pwh, g_wh);       cudaGetSymbolAddress((void**)&pwl, g_wl);
    cudaGetSymbolAddress((void**)&pqh, g_qh);       cudaGetSymbolAddress((void**)&pql, g_ql);
    cudaGetSymbolAddress((void**)&pkh, g_kh);       cudaGetSymbolAddress((void**)&pkl, g_kl);
    cudaGetSymbolAddress((void**)&patf, g_atf);
    cudaGetSymbolAddress((void**)&ps1nh, g_s1nh);   cudaGetSymbolAddress((void**)&ps1nl, g_s1nl);
    cudaGetSymbolAddress((void**)&ppreh, g_preh);   cudaGetSymbolAddress((void**)&pprel, g_prel);
    cudaGetSymbolAddress((void**)&pdots, g_dots);
    cudaGetSymbolAddress((void**)&prowsum, g_rowsum);

    const int ZBIG = 1 << 30;
    const int WN = 512 * 512;
    dim3 T(256);

    split_ctx_kernel<<<dim3(Dn/32, Kn/32, Bn), dim3(32, 8)>>>(ctx, ctx_enc);
    split7_kernel<<<dim3((int)((NELEM_QD + 255)/256), 7), T>>>(Wq, Wk, Wf, We, Wof, Woe,
                                                               slots, slots_enc);
    init_kernel<<<1, 256>>>();

    // merged k-proj (z=0) + q-proj (z=1, nrowsPair=2048, extra y-tiles exit early)
    // all live tiles full -> GUARD=0
    bs_gemm<3, 0><<<dim3(4, 512, 2), T>>>(pksh, pksl, pqsh, pqsl, Dn,
        pwh + 1*WN, pwl + 1*WN, pwh + 0*WN, pwl + 0*WN, Dn,
        nullptr, nullptr, nullptr, 0,
        nullptr, pkh, pkl, (long long)(pqh - pkh), (long long)(pql - pkl), Dn,
        Bn*Kn, Bn*Qn, Dn, Dn, 1.f, 1, 1,
        0, 0, 0, 0, 0, 0, 1);

    // dots: [128 x 4096 x 64] batched (b,h), fp32 out + fused scoring -> GUARD=0
    bs_gemm<3, 0><<<dim3(Kn/128, 1, Bn*Hn), T>>>(pqh, pql, nullptr, nullptr, Dn,
        pkh, pkl, nullptr, nullptr, Dn,
        nullptr, nullptr, nullptr, 0,
        pdots, nullptr, nullptr, 0, 0, Kn,
        Qn, Qn, Kn, Cn, 0.125f, Hn, ZBIG,
        (long long)Qn*Dn, 64, (long long)Kn*Dn, 64,
        (long long)Hn*Qn*Kn, (long long)Qn*Kn, 2);

    topk_kernel   <<<Bn, 128>>>();
    softmax_kernel<<<dim3(Kn/128, Hn, Bn), 128>>>();

    // AV paired (fp16 1-product) + fused key-renorm + split out: rows 264 partial -> GUARD=1
    bs_gemm<1, 1><<<dim3(4, 3, 2*Bn), T>>>(
        (const __nv_bfloat16*)patf, nullptr, nullptr, nullptr, Kn,
        (const __nv_bfloat16*)pcth, nullptr,
        (const __nv_bfloat16*)pceh, nullptr, Kn,
        nullptr, nullptr, prowsum, Hn*KEEPN,
        nullptr, ps1nh, ps1nl, (long long)NELEM_S1, (long long)NELEM_S1, Dn,
        Hn*KEEPN, Hn*KEEPN, Dn, Kn, 1.f, 1, Bn,
        (long long)Hn*KEEPN*Kn, 0, (long long)Dn*Kn, 0,
        (long long)Hn*KEEPN*Dn, 0, 1);

    // per-head contraction paired: [33 x 64 x 512] partial -> GUARD=1
    bs_gemm<3, 1><<<dim3(1, 1, 2*Bn*Hn), T>>>(ps1nh, ps1nl, ps1nh + NELEM_S1, ps1nl + NELEM_S1, Dn,
        pwh + 2*WN, pwl + 2*WN, pwh + 3*WN, pwl + 3*WN, Dn,
        nullptr, nullptr, nullptr, 0,
        nullptr, ppreh, pprel, (long long)NELEM_PRE, (long long)NELEM_PRE, Dn,
        KEEPN, KEEPN, Cn, Dn, 1.f, Hn, Bn*Hn,
        (long long)Hn*KEEPN*Dn, (long long)KEEPN*Dn,
        0, (long long)Cn*Dn,
        (long long)KEEPN*Dn, (long long)Cn, 1);

    // out-proj paired: [528 x 512 x 512] rows partial -> GUARD=1
    bs_gemm<3, 1><<<dim3(4, 5, 2), T>>>(ppreh, pprel, ppreh + NELEM_PRE, pprel + NELEM_PRE, Dn,
        pwh + 4*WN, pwl + 4*WN, pwh + 5*WN, pwl + 5*WN, Dn,
        bof, boe, nullptr, 0,
        outp, nullptr, nullptr, (long long)Bn*KEEPN*Dn, 0, Dn,
        Bn*KEEPN, Bn*KEEPN, Dn, Dn, 1.f, 1, 1,
        0, 0, 0, 0, 0, 0, 0);

    finalize_keep_kernel<<<3, 256>>>(outp + 2*(size_t)Bn*KEEPN*Dn);
}

// round 16
// speedup vs baseline: 1.0581x; 1.0119x over previous
#include <cuda_runtime.h>
#include <cuda_bf16.h>
#include <cuda_fp16.h>
#include <math.h>
#include <stdint.h>

#define Bn 16
#define Qn 128
#define Kn 4096
#define Dn 512
#define Hn 8
#define Cn 64
#define MQn 32
#define KEEPN 33   // MQ + 1

#define NELEM_QD ((size_t)Bn*Qn*Dn)
#define NELEM_KD ((size_t)Bn*Kn*Dn)
#define NELEM_DOTS ((size_t)Bn*Hn*Qn*Kn)
#define NELEM_ATT ((size_t)Bn*Hn*KEEPN*Kn)
#define NELEM_S1 ((size_t)Bn*Hn*KEEPN*Dn)
#define NELEM_PRE ((size_t)Bn*KEEPN*Dn)

// ---------------- scratch (device globals; no allocation allowed) ----------------
static __device__ __nv_bfloat16 g_qsum_h[NELEM_QD], g_qsum_l[NELEM_QD];
static __device__ __nv_bfloat16 g_ksum_h[NELEM_KD], g_ksum_l[NELEM_KD];
static __device__ __half        g_ctxT_h[NELEM_KD];                 // [B,D,K] fp16
static __device__ __half        g_ctxeT_h[NELEM_KD];                // [B,D,K] fp16
static __device__ __nv_bfloat16 g_wh[6*512*512], g_wl[6*512*512]; // Wq Wk Wf We Wof Woe
static __device__ __nv_bfloat16 g_qh[NELEM_QD], g_ql[NELEM_QD];
static __device__ __nv_bfloat16 g_kh[NELEM_KD], g_kl[NELEM_KD];
static __device__ float        g_dots[NELEM_DOTS];
static __device__ __half       g_atf[NELEM_ATT];                 // attn, single fp16 plane
static __device__ __nv_bfloat16 g_s1nh[2][NELEM_S1], g_s1nl[2][NELEM_S1];
static __device__ __nv_bfloat16 g_preh[2][NELEM_PRE], g_prel[2][NELEM_PRE];
static __device__ float g_score[Bn*(Qn-1)];
static __device__ int   g_keep [Bn*KEEPN];
static __device__ float g_rowsum[Bn*Hn*KEEPN];

// ---------------- helpers ----------------
__device__ __forceinline__ uint32_t s2u(const void* p) {
    uint32_t r;
    asm("{ .reg .u64 t; cvta.to.shared.u64 t, %1; cvt.u32.u64 %0, t; }" : "=r"(r) : "l"(p));
    return r;
}
__device__ __forceinline__ void split1(float v, __nv_bfloat16& h, __nv_bfloat16& l) {
    h = __float2bfloat16(v);
    l = __float2bfloat16(v - __bfloat162float(h));
}
template<int F16>
__device__ __forceinline__ void mmaAB(float* d, const uint32_t* a, const uint32_t* b) {
    if (F16)
        asm volatile(
            "mma.sync.aligned.m16n8k16.row.col.f32.f16.f16.f32 "
            "{%0,%1,%2,%3}, {%4,%5,%6,%7}, {%8,%9}, {%0,%1,%2,%3};"
            : "+f"(d[0]), "+f"(d[1]), "+f"(d[2]), "+f"(d[3])
            : "r"(a[0]), "r"(a[1]), "r"(a[2]), "r"(a[3]), "r"(b[0]), "r"(b[1]));
    else
        asm volatile(
            "mma.sync.aligned.m16n8k16.row.col.f32.bf16.bf16.f32 "
            "{%0,%1,%2,%3}, {%4,%5,%6,%7}, {%8,%9}, {%0,%1,%2,%3};"
            : "+f"(d[0]), "+f"(d[1]), "+f"(d[2]), "+f"(d[3])
            : "r"(a[0]), "r"(a[1]), "r"(a[2]), "r"(a[3]), "r"(b[0]), "r"(b[1]));
}
__device__ __forceinline__ void ldsm4(uint32_t& r0, uint32_t& r1, uint32_t& r2, uint32_t& r3,
                                      uint32_t addr) {
    asm volatile("ldmatrix.sync.aligned.m8n8.x4.shared.b16 {%0,%1,%2,%3}, [%4];"
                 : "=r"(r0), "=r"(r1), "=r"(r2), "=r"(r3) : "r"(addr));
}

#define BM 128
#define BN 128
#define BKt 16

// ---------------- kq_gemm: 64x64 warp tiles, 4 warps, PROD=3, full tiles ----------------
// Dedicated to the merged k-proj/q-proj launch. C = A @ B^T, split-bf16 in/out.
// Pairing via z >= zpair (switch operands, offset C, nrows=nrowsPair).
__global__ void __launch_bounds__(128, 2) kq_gemm(
    const __nv_bfloat16* __restrict__ Ah, const __nv_bfloat16* __restrict__ Al,
    const __nv_bfloat16* __restrict__ Ahb, const __nv_bfloat16* __restrict__ Alb,
    int lda,
    const __nv_bfloat16* __restrict__ Bh, const __nv_bfloat16* __restrict__ Bl,
    const __nv_bfloat16* __restrict__ Bhb, const __nv_bfloat16* __restrict__ Blb,
    int ldb,
    __nv_bfloat16* __restrict__ CH, __nv_bfloat16* __restrict__ CL,
    long long sCpair, long long sCpairL, int ldc,
    int nrows, int nrowsPair, int kdim, int zpair)
{
    __shared__ __align__(16) uint4 sbuf[2][4][2][128];

    int z = blockIdx.z;
    if (z >= zpair) {
        Ah = Ahb; Al = Alb;
        Bh = Bhb; Bl = Blb;
        CH += sCpair; CL += sCpairL;
        nrows = nrowsPair;
    }
    const int row0 = blockIdx.y * BM, col0 = blockIdx.x * BN;
    if (row0 >= nrows) return;

    const int tid = threadIdx.x, lane = tid & 31, warp = tid >> 5;
    const int wr = warp >> 1, wc = warp & 1;    // 2x2 warps, 64x64 tiles
    const int g = lane >> 2, t = lane & 3;

    float acc[4][8][4];
    #pragma unroll
    for (int mi = 0; mi < 4; mi++)
        #pragma unroll
        for (int ni = 0; ni < 8; ni++)
            #pragma unroll
            for (int j = 0; j < 4; j++) acc[mi][ni][j] = 0.f;

    // loader: thread handles one row (tid) of each tile, both k-halves
    const __nv_bfloat16 *pAh = Ah + (long long)(row0 + tid) * lda;
    const __nv_bfloat16 *pAl = Al + (long long)(row0 + tid) * lda;
    const __nv_bfloat16 *pBh = Bh + (long long)(col0 + tid) * ldb;
    const __nv_bfloat16 *pBl = Bl + (long long)(col0 + tid) * ldb;
    uint4 rA0, rA1, rA2, rA3, rB0, rB1, rB2, rB3;
    auto ld = [&]() {
        rA0 = *(const uint4*)pAh; rA1 = *(const uint4*)(pAh + 8);
        rA2 = *(const uint4*)pAl; rA3 = *(const uint4*)(pAl + 8);
        rB0 = *(const uint4*)pBh; rB1 = *(const uint4*)(pBh + 8);
        rB2 = *(const uint4*)pBl; rB3 = *(const uint4*)(pBl + 8);
        pAh += BKt; pAl += BKt; pBh += BKt; pBl += BKt;
    };
    auto st = [&](int s) {
        sbuf[s][0][0][tid] = rA0; sbuf[s][0][1][tid] = rA1;
        sbuf[s][1][0][tid] = rA2; sbuf[s][1][1][tid] = rA3;
        sbuf[s][2][0][tid] = rB0; sbuf[s][2][1][tid] = rB1;
        sbuf[s][3][0][tid] = rB2; sbuf[s][3][1][tid] = rB3;
    };

    const uint32_t sb0 = s2u(&sbuf[0][0][0][0]);
    const int a_off = ((lane >> 4) & 1) * 2048 + (((lane >> 3) & 1) * 8 + (lane & 7)) * 16;
    const int bq = lane >> 3;
    const int b_off = (bq & 1) * 2048 + (wc * 64 + (bq >> 1) * 8 + (lane & 7)) * 16;

    auto step = [&](int s) {
        const uint32_t stg = sb0 + s * 16384;
        uint32_t bh4[8][2], bl4[8][2];
        #pragma unroll
        for (int j = 0; j < 4; j++) {
            ldsm4(bh4[2*j][0], bh4[2*j][1], bh4[2*j+1][0], bh4[2*j+1][1],
                  stg + 2 * 4096 + b_off + j * 256);
            ldsm4(bl4[2*j][0], bl4[2*j][1], bl4[2*j+1][0], bl4[2*j+1][1],
                  stg + 3 * 4096 + b_off + j * 256);
        }
        #pragma unroll
        for (int mi = 0; mi < 4; mi++) {
            const uint32_t rowb = (wr * 64 + mi * 16) * 16;
            uint32_t ah4[4], al4[4];
            ldsm4(ah4[0], ah4[1], ah4[2], ah4[3], stg + a_off + rowb);
            ldsm4(al4[0], al4[1], al4[2], al4[3], stg + 4096 + a_off + rowb);
            #pragma unroll
            for (int ni = 0; ni < 8; ni++) {
                mmaAB<0>(acc[mi][ni], ah4, bh4[ni]);
                mmaAB<0>(acc[mi][ni], al4, bh4[ni]);
                mmaAB<0>(acc[mi][ni], ah4, bl4[ni]);
            }
        }
    };

    const int nt = kdim / BKt;
    ld(); st(0);
    __syncthreads();
    for (int it = 0; it < nt; it++) {
        int cur = it & 1;
        if (it + 1 < nt) ld();
        step(cur);
        if (it + 1 < nt) { st(cur ^ 1); __syncthreads(); }
    }

    // epilogue: split bf16 out (all tiles full in N; rows full for live tiles)
    #pragma unroll
    for (int mi = 0; mi < 4; mi++) {
        #pragma unroll
        for (int jj = 0; jj < 2; jj++) {
            int rr = row0 + wr * 64 + mi * 16 + g + jj * 8;
            #pragma unroll
            for (int ni = 0; ni < 8; ni++) {
                int c = col0 + wc * 64 + ni * 8 + 2 * t;
                float v0 = acc[mi][ni][jj * 2 + 0];
                float v1 = acc[mi][ni][jj * 2 + 1];
                __nv_bfloat16 h0, l0, h1, l1;
                split1(v0, h0, l0); split1(v1, h1, l1);
                *(__nv_bfloat162*)(CH + (long long)rr * ldc + c) = __halves2bfloat162(h0, h1);
                *(__nv_bfloat162*)(CL + (long long)rr * ldc + c) = __halves2bfloat162(l0, l1);
            }
        }
    }
}

// ---------------- unified NT split GEMM ----------------
// PROD=3: bf16 3-term (AhBh + AlBh + AhBl). PROD=1: fp16 1-product.
// GUARD=0: all tiles full (no bounds checks in mainloop).
// Pairing: z >= zpair -> switch (A*, B*, bias), offset C, nrows=nrowsPair.
// rowscale: row r scaled by 1/(rowscale[b*rsStride + r] + 1e-8).
// mode: 0 = fp32 out (+bias), 1 = split bf16 h/l out, 2 = fp32 out + fused scoring.
template<int PROD, int GUARD>
__global__ void __launch_bounds__(256, 2) bs_gemm(
    const __nv_bfloat16* __restrict__ Ah, const __nv_bfloat16* __restrict__ Al,
    const __nv_bfloat16* __restrict__ Ahb, const __nv_bfloat16* __restrict__ Alb,
    int lda,
    const __nv_bfloat16* __restrict__ Bh, const __nv_bfloat16* __restrict__ Bl,
    const __nv_bfloat16* __restrict__ Bhb, const __nv_bfloat16* __restrict__ Blb,
    int ldb,
    const float* __restrict__ bias, const float* __restrict__ biasb,
    const float* __restrict__ rowscale, int rsStride,
    float* __restrict__ Cf, __nv_bfloat16* __restrict__ CH, __nv_bfloat16* __restrict__ CL,
    long long sCpair, long long sCpairL, int ldc,
    int nrows, int nrowsPair, int ncols, int kdim, float scale, int zdiv, int zpair,
    long long sAb, long long sAhh, long long sBb, long long sBhh,
    long long sCb, long long sChh, int mode)
{
    __shared__ __align__(16) uint4 sbuf[2][4][2][128];
    __shared__ float scoreBuf[BN + BM];

    int z = blockIdx.z;
    if (z >= zpair) {
        z -= zpair;
        if (Ahb) { Ah = Ahb; Al = Alb; }
        if (Bhb) { Bh = Bhb; Bl = Blb; }
        bias = biasb;
        if (Cf) Cf += sCpair;
        if (CH) { CH += sCpair; CL += sCpairL; }
        nrows = nrowsPair;
    }
    const int row0 = blockIdx.y * BM, col0 = blockIdx.x * BN;
    if (row0 >= nrows || col0 >= ncols) return;

    const int b = z / zdiv, h = z - b * zdiv;
    {
        long long ao = (long long)b * sAb + (long long)h * sAhh;
        long long bo = (long long)b * sBb + (long long)h * sBhh;
        long long co = (long long)b * sCb + (long long)h * sChh;
        Ah += ao; Al += ao;
        Bh += bo; Bl += bo;
        if (Cf) Cf += co;
        if (CH) { CH += co; CL += co; }
    }

    const int tid = threadIdx.x, lane = tid & 31, warp = tid >> 5;
    const int wr = warp >> 2, wc = warp & 3;
    const int g = lane >> 2, t = lane & 3;
    const int lr = tid >> 1, hf = tid & 1;   // loader row / k-half

    const int valid_m = nrows - row0;
    const int valid_n = ncols - col0;
    bool mAct[4], nAct[2];
    #pragma unroll
    for (int mi = 0; mi < 4; mi++) mAct[mi] = !GUARD || (wr * 64 + mi * 16) < valid_m;
    #pragma unroll
    for (int j = 0; j < 2; j++) nAct[j] = !GUARD || (wc * 32 + j * 16) < valid_n;

    float acc[4][4][4];
    #pragma unroll
    for (int mi = 0; mi < 4; mi++)
        #pragma unroll
        for (int ni = 0; ni < 4; ni++)
            #pragma unroll
            for (int j = 0; j < 4; j++) acc[mi][ni][j] = 0.f;

    uint4 rAh, rAl, rBh, rBl;
    const uint4 Z4 = make_uint4(0u, 0u, 0u, 0u);

    const bool aValid = !GUARD || (row0 + lr < nrows);
    const bool bValid = !GUARD || (col0 + lr < ncols);
    const __nv_bfloat16 *pAh, *pAl = nullptr, *pBh, *pBl = nullptr;
    {
        long long ar = (long long)(aValid ? row0 + lr : 0) * lda + hf * 8;
        long long br = (long long)(bValid ? col0 + lr : 0) * ldb + hf * 8;
        pAh = Ah + ar;
        if (PROD == 3) pAl = Al + ar;
        pBh = Bh + br;
        if (PROD == 3) pBl = Bl + br;
    }
    auto ld = [&]() {
        if (aValid) {
            rAh = *(const uint4*)pAh;
            if (PROD == 3) rAl = *(const uint4*)pAl;
        } else { rAh = Z4; rAl = Z4; }
        if (bValid) {
            rBh = *(const uint4*)pBh;
            if (PROD == 3) rBl = *(const uint4*)pBl;
        } else { rBh = Z4; rBl = Z4; }
        pAh += BKt; pBh += BKt;
        if (PROD == 3) { pAl += BKt; pBl += BKt; }
    };
    auto st = [&](int s) {
        sbuf[s][0][hf][lr] = rAh;
        if (PROD == 3) sbuf[s][1][hf][lr] = rAl;
        sbuf[s][2][hf][lr] = rBh;
        if (PROD == 3) sbuf[s][3][hf][lr] = rBl;
    };

    const uint32_t sb0 = s2u(&sbuf[0][0][0][0]);
    const int a_off = ((lane >> 4) & 1) * 2048 + (((lane >> 3) & 1) * 8 + (lane & 7)) * 16;
    const int bq = lane >> 3;
    const int b_off = (bq & 1) * 2048 + (wc * 32 + (bq >> 1) * 8 + (lane & 7)) * 16;

    auto step = [&](int s) {
        const uint32_t stg = sb0 + s * 16384;
        uint32_t bh4[4][2], bl4[4][2];
        #pragma unroll
        for (int j = 0; j < 2; j++) {
            if (GUARD && !nAct[j]) continue;
            ldsm4(bh4[2*j][0], bh4[2*j][1], bh4[2*j+1][0], bh4[2*j+1][1],
                  stg + 2 * 4096 + b_off + j * 256);
            if (PROD == 3)
                ldsm4(bl4[2*j][0], bl4[2*j][1], bl4[2*j+1][0], bl4[2*j+1][1],
                      stg + 3 * 4096 + b_off + j * 256);
        }
        #pragma unroll
        for (int mi = 0; mi < 4; mi++) {
            if (GUARD && !mAct[mi]) continue;
            const uint32_t rowb = (wr * 64 + mi * 16) * 16;
            uint32_t ah4[4], al4[4];
            ldsm4(ah4[0], ah4[1], ah4[2], ah4[3], stg + a_off + rowb);
            if (PROD == 3)
                ldsm4(al4[0], al4[1], al4[2], al4[3], stg + 4096 + a_off + rowb);
            #pragma unroll
            for (int ni = 0; ni < 4; ni++) {
                if (GUARD && !nAct[ni >> 1]) continue;
                if (PROD == 3) {
                    mmaAB<0>(acc[mi][ni], ah4, bh4[ni]);
                    mmaAB<0>(acc[mi][ni], al4, bh4[ni]);
                    mmaAB<0>(acc[mi][ni], ah4, bl4[ni]);
                } else {
                    mmaAB<1>(acc[mi][ni], ah4, bh4[ni]);
                }
            }
        }
    };

    const int nt = kdim / BKt;
    ld(); st(0);
    __syncthreads();
    for (int it = 0; it < nt; it++) {
        int cur = it & 1;
        if (it + 1 < nt) ld();
        step(cur);
        if (it + 1 < nt) { st(cur ^ 1); __syncthreads(); }
    }

    // ---- C epilogue
    if (mode != 2) {
        #pragma unroll
        for (int mi = 0; mi < 4; mi++) {
            #pragma unroll
            for (int jj = 0; jj < 2; jj++) {
                int rr = row0 + wr * 64 + mi * 16 + g + jj * 8;
                if (rr >= nrows) continue;
                float rsc = scale;
                if (rowscale)
                    rsc = scale / (rowscale[(long long)b * rsStride + rr] + 1e-8f);
                #pragma unroll
                for (int ni = 0; ni < 4; ni++) {
                    int c = col0 + wc * 32 + ni * 8 + 2 * t;
                    if (c >= ncols) continue;
                    float v0 = acc[mi][ni][jj * 2 + 0] * rsc;
                    float v1 = acc[mi][ni][jj * 2 + 1] * rsc;
                    if (mode == 1) {
                        __nv_bfloat16 h0, l0, h1, l1;
                        split1(v0, h0, l0); split1(v1, h1, l1);
                        *(__nv_bfloat162*)(CH + (long long)rr * ldc + c) = __halves2bfloat162(h0, h1);
                        *(__nv_bfloat162*)(CL + (long long)rr * ldc + c) = __halves2bfloat162(l0, l1);
                    } else {
                        if (bias) { v0 += bias[c]; v1 += bias[c + 1]; }
                        *(float2*)(Cf + (long long)rr * ldc + c) = make_float2(v0, v1);
                    }
                }
            }
        }
    } else {
        // mode 2: write fp32 dots AND run fused scoring (exp cached into acc)
        #pragma unroll
        for (int mi = 0; mi < 4; mi++) {
            #pragma unroll
            for (int jj = 0; jj < 2; jj++) {
                int rr = row0 + wr * 64 + mi * 16 + g + jj * 8;
                #pragma unroll
                for (int ni = 0; ni < 4; ni++) {
                    int c = col0 + wc * 32 + ni * 8 + 2 * t;
                    float v0 = acc[mi][ni][jj * 2 + 0] * scale;
                    float v1 = acc[mi][ni][jj * 2 + 1] * scale;
                    *(float2*)(Cf + (long long)rr * ldc + c) = make_float2(v0, v1);
                }
            }
        }

        float* colsum = scoreBuf;
        float* rowmax = scoreBuf + BN;
        for (int i = tid; i < BN + BM; i += 256) scoreBuf[i] = 0.f;
        __syncthreads();

        float cs[8];
        #pragma unroll
        for (int q = 0; q < 8; q++) cs[q] = 0.f;
        #pragma unroll
        for (int mi = 0; mi < 4; mi++)
            #pragma unroll
            for (int ni = 0; ni < 4; ni++)
                #pragma unroll
                for (int j = 0; j < 4; j++) {
                    int grow = wr * 64 + mi * 16 + g + 8 * (j >> 1);
                    if (grow != 0) {
                        float e = __expf(acc[mi][ni][j] * scale);
                        acc[mi][ni][j] = e;   // cache for pass 2
                        cs[ni * 2 + (j & 1)] += e;
                    }
                }
        #pragma unroll
        for (int o = 4; o <= 16; o <<= 1)
            #pragma unroll
            for (int q = 0; q < 8; q++)
                cs[q] += __shfl_xor_sync(0xffffffffu, cs[q], o);
        if (g == 0) {
            #pragma unroll
            for (int q = 0; q < 8; q++)
                atomicAdd(&colsum[wc * 32 + (q >> 1) * 8 + 2 * t + (q & 1)], cs[q]);
        }
        __syncthreads();

        float rm[8];
        #pragma unroll
        for (int q = 0; q < 8; q++) rm[q] = 0.f;
        #pragma unroll
        for (int mi = 0; mi < 4; mi++)
            #pragma unroll
            for (int ni = 0; ni < 4; ni++)
                #pragma unroll
                for (int j = 0; j < 4; j++) {
                    int grow = wr * 64 + mi * 16 + g + 8 * (j >> 1);
                    if (grow != 0) {
                        int c = wc * 32 + ni * 8 + 2 * t + (j & 1);
                        float v = acc[mi][ni][j] / colsum[c];
                        int qi = mi * 2 + (j >> 1);
                        rm[qi] = fmaxf(rm[qi], v);
                    }
                }
        #pragma unroll
        for (int o = 1; o <= 2; o <<= 1)
            #pragma unroll
            for (int q = 0; q < 8; q++)
                rm[q] = fmaxf(rm[q], __shfl_xor_sync(0xffffffffu, rm[q], o));
        if (t == 0) {
            #pragma unroll
            for (int q = 0; q < 8; q++)
                atomicMax((int*)&rowmax[wr * 64 + (q >> 1) * 16 + g + 8 * (q & 1)],
                          __float_as_int(rm[q]));
        }
        __syncthreads();
        if (tid >= 1 && tid < BM)
            atomicMax((int*)&g_score[b * (Qn - 1) + tid - 1],
                      __float_as_int(rowmax[tid]));
    }
}

// ---------------- split / transpose ctx & ctx_enc ----------------
__global__ void split_ctx_kernel(const float* __restrict__ ctx, const float* __restrict__ ctxe) {
    __shared__ float tc_[32][33], te_[32][33];
    int bb = blockIdx.z, d0 = blockIdx.x * 32, k0 = blockIdx.y * 32;
    int tx = threadIdx.x, ty = threadIdx.y;
    const float* pc = ctx  + ((long long)bb * Kn + k0) * Dn + d0;
    const float* pe = ctxe + ((long long)bb * Kn + k0) * Dn + d0;
    #pragma unroll
    for (int j = 0; j < 4; j++) {
        int kk = ty + j * 8;
        float c = pc[(long long)kk * Dn + tx];
        float e = pe[(long long)kk * Dn + tx];
        tc_[kk][tx] = c; te_[kk][tx] = e;
        __nv_bfloat16 sh, sl;
        split1(c + e, sh, sl);
        long long o = ((long long)bb * Kn + k0 + kk) * Dn + d0 + tx;
        g_ksum_h[o] = sh; g_ksum_l[o] = sl;
    }
    __syncthreads();
    #pragma unroll
    for (int j = 0; j < 4; j++) {
        int dd = ty + j * 8;
        long long o = ((long long)bb * Dn + d0 + dd) * Kn + k0 + tx;
        g_ctxT_h[o]  = __float2half(tc_[tx][dd]);
        g_ctxeT_h[o] = __float2half(te_[tx][dd]);
    }
}

// ---------------- weight + qsum splits (7 jobs, one launch) ----------------
__global__ void split7_kernel(const float* __restrict__ w0, const float* __restrict__ w1,
                              const float* __restrict__ w2, const float* __restrict__ w3,
                              const float* __restrict__ w4, const float* __restrict__ w5,
                              const float* __restrict__ slots,
                              const float* __restrict__ slots_enc) {
    const int WN = 512 * 512;
    int job = blockIdx.y;
    int i = blockIdx.x * 256 + threadIdx.x;
    if (job < 6) {
        if (i >= WN) return;
        const float* src = (job == 0) ? w0 : (job == 1) ? w1 : (job == 2) ? w2
                         : (job == 3) ? w3 : (job == 4) ? w4 : w5;
        __nv_bfloat16 hh, ll;
        split1(src[i], hh, ll);
        g_wh[job * WN + i] = hh;
        g_wl[job * WN + i] = ll;
    } else {
        if (i >= (int)NELEM_QD) return;
        __nv_bfloat16 hh, ll;
        split1(slots[i] + slots_enc[i], hh, ll);
        g_qsum_h[i] = hh; g_qsum_l[i] = ll;
    }
}

// ---------------- per-launch state reset ----------------
__global__ void init_kernel() {
    for (int i = threadIdx.x; i < Bn*(Qn-1); i += 256) g_score[i] = 0.f;
    for (int i = threadIdx.x; i < Bn*Hn*KEEPN; i += 256) g_rowsum[i] = 0.f;
}

// ---------------- top-32 selection (ties -> lower index) ----------------
__global__ void topk_kernel() {
    int b = blockIdx.x;
    int t = threadIdx.x;   // 128
    __shared__ float sv[128];
    __shared__ float rv[128];
    __shared__ int   ri[128];
    sv[t] = (t < Qn-1) ? g_score[b*(Qn-1) + t] : -INFINITY;
    __syncthreads();
    for (int r = 0; r < MQn; r++) {
        rv[t] = sv[t]; ri[t] = t;
        __syncthreads();
        for (int off = 64; off > 0; off >>= 1) {
            if (t < off) {
                float v2 = rv[t+off]; int i2 = ri[t+off];
                if (v2 > rv[t] || (v2 == rv[t] && i2 < ri[t])) { rv[t] = v2; ri[t] = i2; }
            }
            __syncthreads();
        }
        int win = ri[0];
        if (t == 0) g_keep[b*KEEPN + 1 + r] = win + 1;
        if (t == win) sv[t] = -INFINITY;
        __syncthreads();
    }
    if (t == 0) g_keep[b*KEEPN] = 0;
}

// ---------------- gather + competitive softmax (query axis), fp16 attn + rowsums ----------------
__global__ void softmax_kernel() {
    int b = blockIdx.z, h = blockIdx.y;
    int k = blockIdx.x * 128 + threadIdx.x;
    __shared__ int   kq[KEEPN];
    __shared__ float rs[KEEPN];
    if (threadIdx.x < KEEPN) {
        kq[threadIdx.x] = g_keep[b*KEEPN + threadIdx.x];
        rs[threadIdx.x] = 0.f;
    }
    __syncthreads();
    const float* base = g_dots + ((size_t)((b*Hn + h) * Qn)) * Kn + k;
    float d[KEEPN];
    float m = -INFINITY;
    #pragma unroll
    for (int j = 0; j < KEEPN; j++) {
        d[j] = base[(size_t)kq[j] * Kn];
        m = fmaxf(m, d[j]);
    }
    float s = 0.f;
    #pragma unroll
    for (int j = 0; j < KEEPN; j++) { d[j] = __expf(d[j] - m); s += d[j]; }
    float inv = 1.f / s;
    size_t obase = ((size_t)((b*Hn + h) * KEEPN)) * Kn + k;
    int lane = threadIdx.x & 31;
    #pragma unroll
    for (int j = 0; j < KEEPN; j++) {
        float a = d[j] * inv;
        g_atf[obase + (size_t)j * Kn] = __float2half(a);
        float w = a;
        #pragma unroll
        for (int o = 16; o > 0; o >>= 1) w += __shfl_xor_sync(0xffffffffu, w, o);
        if (lane == 0) atomicAdd(&rs[j], w);
    }
    __syncthreads();
    if (threadIdx.x < KEEPN)
        atomicAdd(&g_rowsum[(b*Hn + h)*KEEPN + threadIdx.x], rs[threadIdx.x]);
}

__global__ void finalize_keep_kernel(float* outp) {
    int i = blockIdx.x * 256 + threadIdx.x;
    if (i < Bn*KEEPN) outp[i] = (float)g_keep[i];
}

// ---------------- launch ----------------
extern "C" void kernel_launch(void* const* d_in, const int* in_sizes, int n_in,
                              void* d_out, int out_size) {
    const float* slots     = (const float*)d_in[0];
    const float* slots_enc = (const float*)d_in[1];
    const float* ctx       = (const float*)d_in[2];
    const float* ctx_enc   = (const float*)d_in[3];
    const float* Wq  = (const float*)d_in[4];
    const float* Wk  = (const float*)d_in[5];
    const float* Wf  = (const float*)d_in[6];
    const float* We  = (const float*)d_in[7];
    const float* Wof = (const float*)d_in[8];
    const float* bof = (const float*)d_in[9];
    const float* Woe = (const float*)d_in[10];
    const float* boe = (const float*)d_in[11];
    float* outp = (float*)d_out;

    __nv_bfloat16 *pqsh, *pqsl, *pksh, *pksl;
    __half *pcth, *pceh, *patf;
    __nv_bfloat16 *pwh, *pwl, *pqh, *pql, *pkh, *pkl;
    __nv_bfloat16 *ps1nh, *ps1nl, *ppreh, *pprel;
    float *pdots, *prowsum;
    cudaGetSymbolAddress((void**)&pqsh, g_qsum_h);  cudaGetSymbolAddress((void**)&pqsl, g_qsum_l);
    cudaGetSymbolAddress((void**)&pksh, g_ksum_h);  cudaGetSymbolAddress((void**)&pksl, g_ksum_l);
    cudaGetSymbolAddress((void**)&pcth, g_ctxT_h);
    cudaGetSymbolAddress((void**)&pceh, g_ctxeT_h);
    cudaGetSymbolAddress((void**)&pwh, g_wh);       cudaGetSymbolAddress((void**)&pwl, g_wl);
    cudaGetSymbolAddress((void**)&pqh, g_qh);       cudaGetSymbolAddress((void**)&pql, g_ql);
    cudaGetSymbolAddress((void**)&pkh, g_kh);       cudaGetSymbolAddress((void**)&pkl, g_kl);
    cudaGetSymbolAddress((void**)&patf, g_atf);
    cudaGetSymbolAddress((void**)&ps1nh, g_s1nh);   cudaGetSymbolAddress((void**)&ps1nl, g_s1nl);
    cudaGetSymbolAddress((void**)&ppreh, g_preh);   cudaGetSymbolAddress((void**)&pprel, g_prel);
    cudaGetSymbolAddress((void**)&pdots, g_dots);
    cudaGetSymbolAddress((void**)&prowsum, g_rowsum);

    const int ZBIG = 1 << 30;
    const int WN = 512 * 512;
    dim3 T(256);

    split_ctx_kernel<<<dim3(Dn/32, Kn/32, Bn), dim3(32, 8)>>>(ctx, ctx_enc);
    split7_kernel<<<dim3((int)((NELEM_QD + 255)/256), 7), T>>>(Wq, Wk, Wf, We, Wof, Woe,
                                                               slots, slots_enc);
    init_kernel<<<1, 256>>>();

    // merged k-proj (z=0) + q-proj (z=1): 64x64-warp-tile kernel, 128 threads
    kq_gemm<<<dim3(4, 512, 2), dim3(128)>>>(pksh, pksl, pqsh, pqsl, Dn,
        pwh + 1*WN, pwl + 1*WN, pwh + 0*WN, pwl + 0*WN, Dn,
        pkh, pkl, (long long)(pqh - pkh), (long long)(pql - pkl), Dn,
        Bn*Kn, Bn*Qn, Dn, 1);

    // dots: [128 x 4096 x 64] batched (b,h), fp32 out + fused scoring -> GUARD=0
    bs_gemm<3, 0><<<dim3(Kn/128, 1, Bn*Hn), T>>>(pqh, pql, nullptr, nullptr, Dn,
        pkh, pkl, nullptr, nullptr, Dn,
        nullptr, nullptr, nullptr, 0,
        pdots, nullptr, nullptr, 0, 0, Kn,
        Qn, Qn, Kn, Cn, 0.125f, Hn, ZBIG,
        (long long)Qn*Dn, 64, (long long)Kn*Dn, 64,
        (long long)Hn*Qn*Kn, (long long)Qn*Kn, 2);

    topk_kernel   <<<Bn, 128>>>();
    softmax_kernel<<<dim3(Kn/128, Hn, Bn), 128>>>();

    // AV paired (fp16 1-product) + fused key-renorm + split out: rows 264 partial -> GUARD=1
    bs_gemm<1, 1><<<dim3(4, 3, 2*Bn), T>>>(
        (const __nv_bfloat16*)patf, nullptr, nullptr, nullptr, Kn,
        (const __nv_bfloat16*)pcth, nullptr,
        (const __nv_bfloat16*)pceh, nullptr, Kn,
        nullptr, nullptr, prowsum, Hn*KEEPN,
        nullptr, ps1nh, ps1nl, (long long)NELEM_S1, (long long)NELEM_S1, Dn,
        Hn*KEEPN, Hn*KEEPN, Dn, Kn, 1.f, 1, Bn,
        (long long)Hn*KEEPN*Kn, 0, (long long)Dn*Kn, 0,
        (long long)Hn*KEEPN*Dn, 0, 1);

    // per-head contraction paired: [33 x 64 x 512] partial -> GUARD=1
    bs_gemm<3, 1><<<dim3(1, 1, 2*Bn*Hn), T>>>(ps1nh, ps1nl, ps1nh + NELEM_S1, ps1nl + NELEM_S1, Dn,
        pwh + 2*WN, pwl + 2*WN, pwh + 3*WN, pwl + 3*WN, Dn,
        nullptr, nullptr, nullptr, 0,
        nullptr, ppreh, pprel, (long long)NELEM_PRE, (long long)NELEM_PRE, Dn,
        KEEPN, KEEPN, Cn, Dn, 1.f, Hn, Bn*Hn,
        (long long)Hn*KEEPN*Dn, (long long)KEEPN*Dn,
        0, (long long)Cn*Dn,
        (long long)KEEPN*Dn, (long long)Cn, 1);

    // out-proj paired: [528 x 512 x 512] rows partial -> GUARD=1
    bs_gemm<3, 1><<<dim3(4, 5, 2), T>>>(ppreh, pprel, ppreh + NELEM_PRE, pprel + NELEM_PRE, Dn,
        pwh + 4*WN, pwl + 4*WN, pwh + 5*WN, pwl + 5*WN, Dn,
        bof, boe, nullptr, 0,
        outp, nullptr, nullptr, (long long)Bn*KEEPN*Dn, 0, Dn,
        Bn*KEEPN, Bn*KEEPN, Dn, Dn, 1.f, 1, 1,
        0, 0, 0, 0, 0, 0, 0);

    finalize_keep_kernel<<<3, 256>>>(outp + 2*(size_t)Bn*KEEPN*Dn);
}

// round 17
// speedup vs baseline: 1.0654x; 1.0069x over previous
#include <cuda_runtime.h>
#include <cuda_bf16.h>
#include <cuda_fp16.h>
#include <math.h>
#include <stdint.h>

#define Bn 16
#define Qn 128
#define Kn 4096
#define Dn 512
#define Hn 8
#define Cn 64
#define MQn 32
#define KEEPN 33   // MQ + 1

#define NELEM_QD ((size_t)Bn*Qn*Dn)
#define NELEM_KD ((size_t)Bn*Kn*Dn)
#define NELEM_DOTS ((size_t)Bn*Hn*Qn*Kn)
#define NELEM_ATT ((size_t)Bn*Hn*KEEPN*Kn)
#define NELEM_S1 ((size_t)Bn*Hn*KEEPN*Dn)
#define NELEM_PRE ((size_t)Bn*KEEPN*Dn)

// ---------------- scratch (device globals; no allocation allowed) ----------------
static __device__ __nv_bfloat16 g_qsum_h[NELEM_QD], g_qsum_l[NELEM_QD];
static __device__ __nv_bfloat16 g_ksum_h[NELEM_KD], g_ksum_l[NELEM_KD];
static __device__ __half        g_ctxT_h[NELEM_KD];                 // [B,D,K] fp16
static __device__ __half        g_ctxeT_h[NELEM_KD];                // [B,D,K] fp16
static __device__ __nv_bfloat16 g_wh[6*512*512], g_wl[6*512*512]; // Wq Wk Wf We Wof Woe
static __device__ __nv_bfloat16 g_qh[NELEM_QD], g_ql[NELEM_QD];
static __device__ __nv_bfloat16 g_kh[NELEM_KD], g_kl[NELEM_KD];
static __device__ float        g_dots[NELEM_DOTS];
static __device__ __half       g_atf[NELEM_ATT];                 // attn, single fp16 plane
static __device__ __nv_bfloat16 g_s1nh[2][NELEM_S1], g_s1nl[2][NELEM_S1];
static __device__ __nv_bfloat16 g_preh[2][NELEM_PRE], g_prel[2][NELEM_PRE];
static __device__ float g_score[Bn*(Qn-1)];
static __device__ int   g_keep [Bn*KEEPN];
static __device__ float g_rowsum[Bn*Hn*KEEPN];

// ---------------- helpers ----------------
__device__ __forceinline__ uint32_t s2u(const void* p) {
    uint32_t r;
    asm("{ .reg .u64 t; cvta.to.shared.u64 t, %1; cvt.u32.u64 %0, t; }" : "=r"(r) : "l"(p));
    return r;
}
__device__ __forceinline__ void split1(float v, __nv_bfloat16& h, __nv_bfloat16& l) {
    h = __float2bfloat16(v);
    l = __float2bfloat16(v - __bfloat162float(h));
}
template<int F16>
__device__ __forceinline__ void mmaAB(float* d, const uint32_t* a, const uint32_t* b) {
    if (F16)
        asm volatile(
            "mma.sync.aligned.m16n8k16.row.col.f32.f16.f16.f32 "
            "{%0,%1,%2,%3}, {%4,%5,%6,%7}, {%8,%9}, {%0,%1,%2,%3};"
            : "+f"(d[0]), "+f"(d[1]), "+f"(d[2]), "+f"(d[3])
            : "r"(a[0]), "r"(a[1]), "r"(a[2]), "r"(a[3]), "r"(b[0]), "r"(b[1]));
    else
        asm volatile(
            "mma.sync.aligned.m16n8k16.row.col.f32.bf16.bf16.f32 "
            "{%0,%1,%2,%3}, {%4,%5,%6,%7}, {%8,%9}, {%0,%1,%2,%3};"
            : "+f"(d[0]), "+f"(d[1]), "+f"(d[2]), "+f"(d[3])
            : "r"(a[0]), "r"(a[1]), "r"(a[2]), "r"(a[3]), "r"(b[0]), "r"(b[1]));
}
__device__ __forceinline__ void ldsm4(uint32_t& r0, uint32_t& r1, uint32_t& r2, uint32_t& r3,
                                      uint32_t addr) {
    asm volatile("ldmatrix.sync.aligned.m8n8.x4.shared.b16 {%0,%1,%2,%3}, [%4];"
                 : "=r"(r0), "=r"(r1), "=r"(r2), "=r"(r3) : "r"(addr));
}

#define BM 128
#define BN 128
#define BKt 16

// ---------------- kq_gemm: BM=128 x BN=256 CTA, 8 warps of 64x64, PROD=3 ----------------
// Dedicated merged k-proj/q-proj. C = A @ B^T, split-bf16 in/out, all live tiles full.
// smem stage (24KB): Ah[2hf][128r] | Al | Bh[2hf][256r] | Bl ; two stages = 48KB.
#define KQ_AH 0
#define KQ_AL 4096
#define KQ_BH 8192
#define KQ_BL 16384
#define KQ_STG 24576

__global__ void __launch_bounds__(256, 1) kq_gemm(
    const __nv_bfloat16* __restrict__ Ah, const __nv_bfloat16* __restrict__ Al,
    const __nv_bfloat16* __restrict__ Ahb, const __nv_bfloat16* __restrict__ Alb,
    int lda,
    const __nv_bfloat16* __restrict__ Bh, const __nv_bfloat16* __restrict__ Bl,
    const __nv_bfloat16* __restrict__ Bhb, const __nv_bfloat16* __restrict__ Blb,
    int ldb,
    __nv_bfloat16* __restrict__ CH, __nv_bfloat16* __restrict__ CL,
    long long sCpair, long long sCpairL, int ldc,
    int nrows, int nrowsPair, int kdim, int zpair)
{
    __shared__ __align__(16) uint4 sbuf[2][KQ_STG / 16];

    int z = blockIdx.z;
    if (z >= zpair) {
        Ah = Ahb; Al = Alb;
        Bh = Bhb; Bl = Blb;
        CH += sCpair; CL += sCpairL;
        nrows = nrowsPair;
    }
    const int row0 = blockIdx.y * BM, col0 = blockIdx.x * 256;
    if (row0 >= nrows) return;

    const int tid = threadIdx.x, lane = tid & 31, warp = tid >> 5;
    const int wr = warp >> 2, wc = warp & 3;    // 2 x 4 warps, 64x64 tiles
    const int g = lane >> 2, t = lane & 3;
    const int lr = tid >> 1, hf = tid & 1;      // A loader: 128 rows x 2 hf

    float acc[4][8][4];
    #pragma unroll
    for (int mi = 0; mi < 4; mi++)
        #pragma unroll
        for (int ni = 0; ni < 8; ni++)
            #pragma unroll
            for (int j = 0; j < 4; j++) acc[mi][ni][j] = 0.f;

    // loaders: A (this thread: one row, one hf, both planes); B (one row, both hf, both planes)
    const __nv_bfloat16 *pAh = Ah + (long long)(row0 + lr) * lda + hf * 8;
    const __nv_bfloat16 *pAl = Al + (long long)(row0 + lr) * lda + hf * 8;
    const __nv_bfloat16 *pBh = Bh + (long long)(col0 + tid) * ldb;
    const __nv_bfloat16 *pBl = Bl + (long long)(col0 + tid) * ldb;
    uint4 rA0, rA1, rB0, rB1, rB2, rB3;
    auto ld = [&]() {
        rA0 = *(const uint4*)pAh;
        rA1 = *(const uint4*)pAl;
        rB0 = *(const uint4*)pBh;
        rB1 = *(const uint4*)(pBh + 8);
        rB2 = *(const uint4*)pBl;
        rB3 = *(const uint4*)(pBl + 8);
        pAh += BKt; pAl += BKt; pBh += BKt; pBl += BKt;
    };
    auto st = [&](int s) {
        char* base = (char*)&sbuf[s][0];
        *(uint4*)(base + KQ_AH + hf * 2048 + lr * 16) = rA0;
        *(uint4*)(base + KQ_AL + hf * 2048 + lr * 16) = rA1;
        *(uint4*)(base + KQ_BH + 0    + tid * 16)     = rB0;   // hf0
        *(uint4*)(base + KQ_BH + 4096 + tid * 16)     = rB1;   // hf1
        *(uint4*)(base + KQ_BL + 0    + tid * 16)     = rB2;
        *(uint4*)(base + KQ_BL + 4096 + tid * 16)     = rB3;
    };

    const uint32_t sb0 = s2u(&sbuf[0][0]);
    const int a_off = ((lane >> 4) & 1) * 2048 + (((lane >> 3) & 1) * 8 + (lane & 7)) * 16;
    const int bq = lane >> 3;
    const int b_off = (bq & 1) * 4096 + (wc * 64 + (bq >> 1) * 8 + (lane & 7)) * 16;

    auto step = [&](int s) {
        const uint32_t stg = sb0 + s * KQ_STG;
        uint32_t bh4[8][2], bl4[8][2];
        #pragma unroll
        for (int j = 0; j < 4; j++) {
            ldsm4(bh4[2*j][0], bh4[2*j][1], bh4[2*j+1][0], bh4[2*j+1][1],
                  stg + KQ_BH + b_off + j * 256);
            ldsm4(bl4[2*j][0], bl4[2*j][1], bl4[2*j+1][0], bl4[2*j+1][1],
                  stg + KQ_BL + b_off + j * 256);
        }
        #pragma unroll
        for (int mi = 0; mi < 4; mi++) {
            const uint32_t rowb = (wr * 64 + mi * 16) * 16;
            uint32_t ah4[4], al4[4];
            ldsm4(ah4[0], ah4[1], ah4[2], ah4[3], stg + KQ_AH + a_off + rowb);
            ldsm4(al4[0], al4[1], al4[2], al4[3], stg + KQ_AL + a_off + rowb);
            #pragma unroll
            for (int ni = 0; ni < 8; ni++) {
                mmaAB<0>(acc[mi][ni], ah4, bh4[ni]);
                mmaAB<0>(acc[mi][ni], al4, bh4[ni]);
                mmaAB<0>(acc[mi][ni], ah4, bl4[ni]);
            }
        }
    };

    const int nt = kdim / BKt;
    ld(); st(0);
    __syncthreads();
    for (int it = 0; it < nt; it++) {
        int cur = it & 1;
        if (it + 1 < nt) ld();
        step(cur);
        if (it + 1 < nt) { st(cur ^ 1); __syncthreads(); }
    }

    // epilogue: split bf16 out; all live tiles full
    #pragma unroll
    for (int mi = 0; mi < 4; mi++) {
        #pragma unroll
        for (int jj = 0; jj < 2; jj++) {
            int rr = row0 + wr * 64 + mi * 16 + g + jj * 8;
            #pragma unroll
            for (int ni = 0; ni < 8; ni++) {
                int c = col0 + wc * 64 + ni * 8 + 2 * t;
                float v0 = acc[mi][ni][jj * 2 + 0];
                float v1 = acc[mi][ni][jj * 2 + 1];
                __nv_bfloat16 h0, l0, h1, l1;
                split1(v0, h0, l0); split1(v1, h1, l1);
                *(__nv_bfloat162*)(CH + (long long)rr * ldc + c) = __halves2bfloat162(h0, h1);
                *(__nv_bfloat162*)(CL + (long long)rr * ldc + c) = __halves2bfloat162(l0, l1);
            }
        }
    }
}

// ---------------- unified NT split GEMM ----------------
// PROD=3: bf16 3-term (AhBh + AlBh + AhBl). PROD=1: fp16 1-product.
// GUARD=0: all tiles full. Pairing via z >= zpair. rowscale: 1/(rs+1e-8).
// mode: 0 = fp32 out (+bias), 1 = split bf16 h/l out, 2 = fp32 out + fused scoring.
template<int PROD, int GUARD>
__global__ void __launch_bounds__(256, 2) bs_gemm(
    const __nv_bfloat16* __restrict__ Ah, const __nv_bfloat16* __restrict__ Al,
    const __nv_bfloat16* __restrict__ Ahb, const __nv_bfloat16* __restrict__ Alb,
    int lda,
    const __nv_bfloat16* __restrict__ Bh, const __nv_bfloat16* __restrict__ Bl,
    const __nv_bfloat16* __restrict__ Bhb, const __nv_bfloat16* __restrict__ Blb,
    int ldb,
    const float* __restrict__ bias, const float* __restrict__ biasb,
    const float* __restrict__ rowscale, int rsStride,
    float* __restrict__ Cf, __nv_bfloat16* __restrict__ CH, __nv_bfloat16* __restrict__ CL,
    long long sCpair, long long sCpairL, int ldc,
    int nrows, int nrowsPair, int ncols, int kdim, float scale, int zdiv, int zpair,
    long long sAb, long long sAhh, long long sBb, long long sBhh,
    long long sCb, long long sChh, int mode)
{
    __shared__ __align__(16) uint4 sbuf[2][4][2][128];
    __shared__ float scoreBuf[BN + BM];

    int z = blockIdx.z;
    if (z >= zpair) {
        z -= zpair;
        if (Ahb) { Ah = Ahb; Al = Alb; }
        if (Bhb) { Bh = Bhb; Bl = Blb; }
        bias = biasb;
        if (Cf) Cf += sCpair;
        if (CH) { CH += sCpair; CL += sCpairL; }
        nrows = nrowsPair;
    }
    const int row0 = blockIdx.y * BM, col0 = blockIdx.x * BN;
    if (row0 >= nrows || col0 >= ncols) return;

    const int b = z / zdiv, h = z - b * zdiv;
    {
        long long ao = (long long)b * sAb + (long long)h * sAhh;
        long long bo = (long long)b * sBb + (long long)h * sBhh;
        long long co = (long long)b * sCb + (long long)h * sChh;
        Ah += ao; Al += ao;
        Bh += bo; Bl += bo;
        if (Cf) Cf += co;
        if (CH) { CH += co; CL += co; }
    }

    const int tid = threadIdx.x, lane = tid & 31, warp = tid >> 5;
    const int wr = warp >> 2, wc = warp & 3;
    const int g = lane >> 2, t = lane & 3;
    const int lr = tid >> 1, hf = tid & 1;   // loader row / k-half

    const int valid_m = nrows - row0;
    const int valid_n = ncols - col0;
    bool mAct[4], nAct[2];
    #pragma unroll
    for (int mi = 0; mi < 4; mi++) mAct[mi] = !GUARD || (wr * 64 + mi * 16) < valid_m;
    #pragma unroll
    for (int j = 0; j < 2; j++) nAct[j] = !GUARD || (wc * 32 + j * 16) < valid_n;

    float acc[4][4][4];
    #pragma unroll
    for (int mi = 0; mi < 4; mi++)
        #pragma unroll
        for (int ni = 0; ni < 4; ni++)
            #pragma unroll
            for (int j = 0; j < 4; j++) acc[mi][ni][j] = 0.f;

    uint4 rAh, rAl, rBh, rBl;
    const uint4 Z4 = make_uint4(0u, 0u, 0u, 0u);

    const bool aValid = !GUARD || (row0 + lr < nrows);
    const bool bValid = !GUARD || (col0 + lr < ncols);
    const __nv_bfloat16 *pAh, *pAl = nullptr, *pBh, *pBl = nullptr;
    {
        long long ar = (long long)(aValid ? row0 + lr : 0) * lda + hf * 8;
        long long br = (long long)(bValid ? col0 + lr : 0) * ldb + hf * 8;
        pAh = Ah + ar;
        if (PROD == 3) pAl = Al + ar;
        pBh = Bh + br;
        if (PROD == 3) pBl = Bl + br;
    }
    auto ld = [&]() {
        if (aValid) {
            rAh = *(const uint4*)pAh;
            if (PROD == 3) rAl = *(const uint4*)pAl;
        } else { rAh = Z4; rAl = Z4; }
        if (bValid) {
            rBh = *(const uint4*)pBh;
            if (PROD == 3) rBl = *(const uint4*)pBl;
        } else { rBh = Z4; rBl = Z4; }
        pAh += BKt; pBh += BKt;
        if (PROD == 3) { pAl += BKt; pBl += BKt; }
    };
    auto st = [&](int s) {
        sbuf[s][0][hf][lr] = rAh;
        if (PROD == 3) sbuf[s][1][hf][lr] = rAl;
        sbuf[s][2][hf][lr] = rBh;
        if (PROD == 3) sbuf[s][3][hf][lr] = rBl;
    };

    const uint32_t sb0 = s2u(&sbuf[0][0][0][0]);
    const int a_off = ((lane >> 4) & 1) * 2048 + (((lane >> 3) & 1) * 8 + (lane & 7)) * 16;
    const int bq = lane >> 3;
    const int b_off = (bq & 1) * 2048 + (wc * 32 + (bq >> 1) * 8 + (lane & 7)) * 16;

    auto step = [&](int s) {
        const uint32_t stg = sb0 + s * 16384;
        uint32_t bh4[4][2], bl4[4][2];
        #pragma unroll
        for (int j = 0; j < 2; j++) {
            if (GUARD && !nAct[j]) continue;
            ldsm4(bh4[2*j][0], bh4[2*j][1], bh4[2*j+1][0], bh4[2*j+1][1],
                  stg + 2 * 4096 + b_off + j * 256);
            if (PROD == 3)
                ldsm4(bl4[2*j][0], bl4[2*j][1], bl4[2*j+1][0], bl4[2*j+1][1],
                      stg + 3 * 4096 + b_off + j * 256);
        }
        #pragma unroll
        for (int mi = 0; mi < 4; mi++) {
            if (GUARD && !mAct[mi]) continue;
            const uint32_t rowb = (wr * 64 + mi * 16) * 16;
            uint32_t ah4[4], al4[4];
            ldsm4(ah4[0], ah4[1], ah4[2], ah4[3], stg + a_off + rowb);
            if (PROD == 3)
                ldsm4(al4[0], al4[1], al4[2], al4[3], stg + 4096 + a_off + rowb);
            #pragma unroll
            for (int ni = 0; ni < 4; ni++) {
                if (GUARD && !nAct[ni >> 1]) continue;
                if (PROD == 3) {
                    mmaAB<0>(acc[mi][ni], ah4, bh4[ni]);
                    mmaAB<0>(acc[mi][ni], al4, bh4[ni]);
                    mmaAB<0>(acc[mi][ni], ah4, bl4[ni]);
                } else {
                    mmaAB<1>(acc[mi][ni], ah4, bh4[ni]);
                }
            }
        }
    };

    const int nt = kdim / BKt;
    ld(); st(0);
    __syncthreads();
    for (int it = 0; it < nt; it++) {
        int cur = it & 1;
        if (it + 1 < nt) ld();
        step(cur);
        if (it + 1 < nt) { st(cur ^ 1); __syncthreads(); }
    }

    // ---- C epilogue
    if (mode != 2) {
        #pragma unroll
        for (int mi = 0; mi < 4; mi++) {
            #pragma unroll
            for (int jj = 0; jj < 2; jj++) {
                int rr = row0 + wr * 64 + mi * 16 + g + jj * 8;
                if (rr >= nrows) continue;
                float rsc = scale;
                if (rowscale)
                    rsc = scale / (rowscale[(long long)b * rsStride + rr] + 1e-8f);
                #pragma unroll
                for (int ni = 0; ni < 4; ni++) {
                    int c = col0 + wc * 32 + ni * 8 + 2 * t;
                    if (c >= ncols) continue;
                    float v0 = acc[mi][ni][jj * 2 + 0] * rsc;
                    float v1 = acc[mi][ni][jj * 2 + 1] * rsc;
                    if (mode == 1) {
                        __nv_bfloat16 h0, l0, h1, l1;
                        split1(v0, h0, l0); split1(v1, h1, l1);
                        *(__nv_bfloat162*)(CH + (long long)rr * ldc + c) = __halves2bfloat162(h0, h1);
                        *(__nv_bfloat162*)(CL + (long long)rr * ldc + c) = __halves2bfloat162(l0, l1);
                    } else {
                        if (bias) { v0 += bias[c]; v1 += bias[c + 1]; }
                        *(float2*)(Cf + (long long)rr * ldc + c) = make_float2(v0, v1);
                    }
                }
            }
        }
    } else {
        // mode 2: write fp32 dots AND run fused scoring (exp cached into acc)
        #pragma unroll
        for (int mi = 0; mi < 4; mi++) {
            #pragma unroll
            for (int jj = 0; jj < 2; jj++) {
                int rr = row0 + wr * 64 + mi * 16 + g + jj * 8;
                #pragma unroll
                for (int ni = 0; ni < 4; ni++) {
                    int c = col0 + wc * 32 + ni * 8 + 2 * t;
                    float v0 = acc[mi][ni][jj * 2 + 0] * scale;
                    float v1 = acc[mi][ni][jj * 2 + 1] * scale;
                    *(float2*)(Cf + (long long)rr * ldc + c) = make_float2(v0, v1);
                }
            }
        }

        float* colsum = scoreBuf;
        float* rowmax = scoreBuf + BN;
        for (int i = tid; i < BN + BM; i += 256) scoreBuf[i] = 0.f;
        __syncthreads();

        float cs[8];
        #pragma unroll
        for (int q = 0; q < 8; q++) cs[q] = 0.f;
        #pragma unroll
        for (int mi = 0; mi < 4; mi++)
            #pragma unroll
            for (int ni = 0; ni < 4; ni++)
                #pragma unroll
                for (int j = 0; j < 4; j++) {
                    int grow = wr * 64 + mi * 16 + g + 8 * (j >> 1);
                    if (grow != 0) {
                        float e = __expf(acc[mi][ni][j] * scale);
                        acc[mi][ni][j] = e;   // cache for pass 2
                        cs[ni * 2 + (j & 1)] += e;
                    }
                }
        #pragma unroll
        for (int o = 4; o <= 16; o <<= 1)
            #pragma unroll
            for (int q = 0; q < 8; q++)
                cs[q] += __shfl_xor_sync(0xffffffffu, cs[q], o);
        if (g == 0) {
            #pragma unroll
            for (int q = 0; q < 8; q++)
                atomicAdd(&colsum[wc * 32 + (q >> 1) * 8 + 2 * t + (q & 1)], cs[q]);
        }
        __syncthreads();

        float rm[8];
        #pragma unroll
        for (int q = 0; q < 8; q++) rm[q] = 0.f;
        #pragma unroll
        for (int mi = 0; mi < 4; mi++)
            #pragma unroll
            for (int ni = 0; ni < 4; ni++)
                #pragma unroll
                for (int j = 0; j < 4; j++) {
                    int grow = wr * 64 + mi * 16 + g + 8 * (j >> 1);
                    if (grow != 0) {
                        int c = wc * 32 + ni * 8 + 2 * t + (j & 1);
                        float v = acc[mi][ni][j] / colsum[c];
                        int qi = mi * 2 + (j >> 1);
                        rm[qi] = fmaxf(rm[qi], v);
                    }
                }
        #pragma unroll
        for (int o = 1; o <= 2; o <<= 1)
            #pragma unroll
            for (int q = 0; q < 8; q++)
                rm[q] = fmaxf(rm[q], __shfl_xor_sync(0xffffffffu, rm[q], o));
        if (t == 0) {
            #pragma unroll
            for (int q = 0; q < 8; q++)
                atomicMax((int*)&rowmax[wr * 64 + (q >> 1) * 16 + g + 8 * (q & 1)],
                          __float_as_int(rm[q]));
        }
        __syncthreads();
        if (tid >= 1 && tid < BM)
            atomicMax((int*)&g_score[b * (Qn - 1) + tid - 1],
                      __float_as_int(rowmax[tid]));
    }
}

// ---------------- split / transpose ctx & ctx_enc ----------------
__global__ void split_ctx_kernel(const float* __restrict__ ctx, const float* __restrict__ ctxe) {
    __shared__ float tc_[32][33], te_[32][33];
    int bb = blockIdx.z, d0 = blockIdx.x * 32, k0 = blockIdx.y * 32;
    int tx = threadIdx.x, ty = threadIdx.y;
    const float* pc = ctx  + ((long long)bb * Kn + k0) * Dn + d0;
    const float* pe = ctxe + ((long long)bb * Kn + k0) * Dn + d0;
    #pragma unroll
    for (int j = 0; j < 4; j++) {
        int kk = ty + j * 8;
        float c = pc[(long long)kk * Dn + tx];
        float e = pe[(long long)kk * Dn + tx];
        tc_[kk][tx] = c; te_[kk][tx] = e;
        __nv_bfloat16 sh, sl;
        split1(c + e, sh, sl);
        long long o = ((long long)bb * Kn + k0 + kk) * Dn + d0 + tx;
        g_ksum_h[o] = sh; g_ksum_l[o] = sl;
    }
    __syncthreads();
    #pragma unroll
    for (int j = 0; j < 4; j++) {
        int dd = ty + j * 8;
        long long o = ((long long)bb * Dn + d0 + dd) * Kn + k0 + tx;
        g_ctxT_h[o]  = __float2half(tc_[tx][dd]);
        g_ctxeT_h[o] = __float2half(te_[tx][dd]);
    }
}

// ---------------- weight + qsum splits (7 jobs, one launch) ----------------
__global__ void split7_kernel(const float* __restrict__ w0, const float* __restrict__ w1,
                              const float* __restrict__ w2, const float* __restrict__ w3,
                              const float* __restrict__ w4, const float* __restrict__ w5,
                              const float* __restrict__ slots,
                              const float* __restrict__ slots_enc) {
    const int WN = 512 * 512;
    int job = blockIdx.y;
    int i = blockIdx.x * 256 + threadIdx.x;
    if (job < 6) {
        if (i >= WN) return;
        const float* src = (job == 0) ? w0 : (job == 1) ? w1 : (job == 2) ? w2
                         : (job == 3) ? w3 : (job == 4) ? w4 : w5;
        __nv_bfloat16 hh, ll;
        split1(src[i], hh, ll);
        g_wh[job * WN + i] = hh;
        g_wl[job * WN + i] = ll;
    } else {
        if (i >= (int)NELEM_QD) return;
        __nv_bfloat16 hh, ll;
        split1(slots[i] + slots_enc[i], hh, ll);
        g_qsum_h[i] = hh; g_qsum_l[i] = ll;
    }
}

// ---------------- per-launch state reset ----------------
__global__ void init_kernel() {
    for (int i = threadIdx.x; i < Bn*(Qn-1); i += 256) g_score[i] = 0.f;
    for (int i = threadIdx.x; i < Bn*Hn*KEEPN; i += 256) g_rowsum[i] = 0.f;
}

// ---------------- top-32 selection (ties -> lower index) ----------------
__global__ void topk_kernel() {
    int b = blockIdx.x;
    int t = threadIdx.x;   // 128
    __shared__ float sv[128];
    __shared__ float rv[128];
    __shared__ int   ri[128];
    sv[t] = (t < Qn-1) ? g_score[b*(Qn-1) + t] : -INFINITY;
    __syncthreads();
    for (int r = 0; r < MQn; r++) {
        rv[t] = sv[t]; ri[t] = t;
        __syncthreads();
        for (int off = 64; off > 0; off >>= 1) {
            if (t < off) {
                float v2 = rv[t+off]; int i2 = ri[t+off];
                if (v2 > rv[t] || (v2 == rv[t] && i2 < ri[t])) { rv[t] = v2; ri[t] = i2; }
            }
            __syncthreads();
        }
        int win = ri[0];
        if (t == 0) g_keep[b*KEEPN + 1 + r] = win + 1;
        if (t == win) sv[t] = -INFINITY;
        __syncthreads();
    }
    if (t == 0) g_keep[b*KEEPN] = 0;
}

// ---------------- gather + competitive softmax (query axis), fp16 attn + rowsums ----------------
__global__ void softmax_kernel() {
    int b = blockIdx.z, h = blockIdx.y;
    int k = blockIdx.x * 128 + threadIdx.x;
    __shared__ int   kq[KEEPN];
    __shared__ float rs[KEEPN];
    if (threadIdx.x < KEEPN) {
        kq[threadIdx.x] = g_keep[b*KEEPN + threadIdx.x];
        rs[threadIdx.x] = 0.f;
    }
    __syncthreads();
    const float* base = g_dots + ((size_t)((b*Hn + h) * Qn)) * Kn + k;
    float d[KEEPN];
    float m = -INFINITY;
    #pragma unroll
    for (int j = 0; j < KEEPN; j++) {
        d[j] = base[(size_t)kq[j] * Kn];
        m = fmaxf(m, d[j]);
    }
    float s = 0.f;
    #pragma unroll
    for (int j = 0; j < KEEPN; j++) { d[j] = __expf(d[j] - m); s += d[j]; }
    float inv = 1.f / s;
    size_t obase = ((size_t)((b*Hn + h) * KEEPN)) * Kn + k;
    int lane = threadIdx.x & 31;
    #pragma unroll
    for (int j = 0; j < KEEPN; j++) {
        float a = d[j] * inv;
        g_atf[obase + (size_t)j * Kn] = __float2half(a);
        float w = a;
        #pragma unroll
        for (int o = 16; o > 0; o >>= 1) w += __shfl_xor_sync(0xffffffffu, w, o);
        if (lane == 0) atomicAdd(&rs[j], w);
    }
    __syncthreads();
    if (threadIdx.x < KEEPN)
        atomicAdd(&g_rowsum[(b*Hn + h)*KEEPN + threadIdx.x], rs[threadIdx.x]);
}

__global__ void finalize_keep_kernel(float* outp) {
    int i = blockIdx.x * 256 + threadIdx.x;
    if (i < Bn*KEEPN) outp[i] = (float)g_keep[i];
}

// ---------------- launch ----------------
extern "C" void kernel_launch(void* const* d_in, const int* in_sizes, int n_in,
                              void* d_out, int out_size) {
    const float* slots     = (const float*)d_in[0];
    const float* slots_enc = (const float*)d_in[1];
    const float* ctx       = (const float*)d_in[2];
    const float* ctx_enc   = (const float*)d_in[3];
    const float* Wq  = (const float*)d_in[4];
    const float* Wk  = (const float*)d_in[5];
    const float* Wf  = (const float*)d_in[6];
    const float* We  = (const float*)d_in[7];
    const float* Wof = (const float*)d_in[8];
    const float* bof = (const float*)d_in[9];
    const float* Woe = (const float*)d_in[10];
    const float* boe = (const float*)d_in[11];
    float* outp = (float*)d_out;

    __nv_bfloat16 *pqsh, *pqsl, *pksh, *pksl;
    __half *pcth, *pceh, *patf;
    __nv_bfloat16 *pwh, *pwl, *pqh, *pql, *pkh, *pkl;
    __nv_bfloat16 *ps1nh, *ps1nl, *ppreh, *pprel;
    float *pdots, *prowsum;
    cudaGetSymbolAddress((void**)&pqsh, g_qsum_h);  cudaGetSymbolAddress((void**)&pqsl, g_qsum_l);
    cudaGetSymbolAddress((void**)&pksh, g_ksum_h);  cudaGetSymbolAddress((void**)&pksl, g_ksum_l);
    cudaGetSymbolAddress((void**)&pcth, g_ctxT_h);
    cudaGetSymbolAddress((void**)&pceh, g_ctxeT_h);
    cudaGetSymbolAddress((void**)&pwh, g_wh);       cudaGetSymbolAddress((void**)&pwl, g_wl);
    cudaGetSymbolAddress((void**)&pqh, g_qh);       cudaGetSymbolAddress((void**)&pql, g_ql);
    cudaGetSymbolAddress((void**)&pkh, g_kh);       cudaGetSymbolAddress((void**)&pkl, g_kl);
    cudaGetSymbolAddress((void**)&patf, g_atf);
    cudaGetSymbolAddress((void**)&ps1nh, g_s1nh);   cudaGetSymbolAddress((void**)&ps1nl, g_s1nl);
    cudaGetSymbolAddress((void**)&ppreh, g_preh);   cudaGetSymbolAddress((void**)&pprel, g_prel);
    cudaGetSymbolAddress((void**)&pdots, g_dots);
    cudaGetSymbolAddress((void**)&prowsum, g_rowsum);

    const int ZBIG = 1 << 30;
    const int WN = 512 * 512;
    dim3 T(256);

    split_ctx_kernel<<<dim3(Dn/32, Kn/32, Bn), dim3(32, 8)>>>(ctx, ctx_enc);
    split7_kernel<<<dim3((int)((NELEM_QD + 255)/256), 7), T>>>(Wq, Wk, Wf, We, Wof, Woe,
                                                               slots, slots_enc);
    init_kernel<<<1, 256>>>();

    // merged k-proj (z=0) + q-proj (z=1): 128x256 CTA tiles, 256 threads
    kq_gemm<<<dim3(2, 512, 2), T>>>(pksh, pksl, pqsh, pqsl, Dn,
        pwh + 1*WN, pwl + 1*WN, pwh + 0*WN, pwl + 0*WN, Dn,
        pkh, pkl, (long long)(pqh - pkh), (long long)(pql - pkl), Dn,
        Bn*Kn, Bn*Qn, Dn, 1);

    // dots: [128 x 4096 x 64] batched (b,h), fp32 out + fused scoring -> GUARD=0
    bs_gemm<3, 0><<<dim3(Kn/128, 1, Bn*Hn), T>>>(pqh, pql, nullptr, nullptr, Dn,
        pkh, pkl, nullptr, nullptr, Dn,
        nullptr, nullptr, nullptr, 0,
        pdots, nullptr, nullptr, 0, 0, Kn,
        Qn, Qn, Kn, Cn, 0.125f, Hn, ZBIG,
        (long long)Qn*Dn, 64, (long long)Kn*Dn, 64,
        (long long)Hn*Qn*Kn, (long long)Qn*Kn, 2);

    topk_kernel   <<<Bn, 128>>>();
    softmax_kernel<<<dim3(Kn/128, Hn, Bn), 128>>>();

    // AV paired (fp16 1-product) + fused key-renorm + split out: rows 264 partial -> GUARD=1
    bs_gemm<1, 1><<<dim3(4, 3, 2*Bn), T>>>(
        (const __nv_bfloat16*)patf, nullptr, nullptr, nullptr, Kn,
        (const __nv_bfloat16*)pcth, nullptr,
        (const __nv_bfloat16*)pceh, nullptr, Kn,
        nullptr, nullptr, prowsum, Hn*KEEPN,
        nullptr, ps1nh, ps1nl, (long long)NELEM_S1, (long long)NELEM_S1, Dn,
        Hn*KEEPN, Hn*KEEPN, Dn, Kn, 1.f, 1, Bn,
        (long long)Hn*KEEPN*Kn, 0, (long long)Dn*Kn, 0,
        (long long)Hn*KEEPN*Dn, 0, 1);

    // per-head contraction paired: [33 x 64 x 512] partial -> GUARD=1
    bs_gemm<3, 1><<<dim3(1, 1, 2*Bn*Hn), T>>>(ps1nh, ps1nl, ps1nh + NELEM_S1, ps1nl + NELEM_S1, Dn,
        pwh + 2*WN, pwl + 2*WN, pwh + 3*WN, pwl + 3*WN, Dn,
        nullptr, nullptr, nullptr, 0,
        nullptr, ppreh, pprel, (long long)NELEM_PRE, (long long)NELEM_PRE, Dn,
        KEEPN, KEEPN, Cn, Dn, 1.f, Hn, Bn*Hn,
        (long long)Hn*KEEPN*Dn, (long long)KEEPN*Dn,
        0, (long long)Cn*Dn,
        (long long)KEEPN*Dn, (long long)Cn, 1);

    // out-proj paired: [528 x 512 x 512] rows partial -> GUARD=1
    bs_gemm<3, 1><<<dim3(4, 5, 2), T>>>(ppreh, pprel, ppreh + NELEM_PRE, pprel + NELEM_PRE, Dn,
        pwh + 4*WN, pwl + 4*WN, pwh + 5*WN, pwl + 5*WN, Dn,
        bof, boe, nullptr, 0,
        outp, nullptr, nullptr, (long long)Bn*KEEPN*Dn, 0, Dn,
        Bn*KEEPN, Bn*KEEPN, Dn, Dn, 1.f, 1, 1,
        0, 0, 0, 0, 0, 0, 0);

    finalize_keep_kernel<<<3, 256>>>(outp + 2*(size_t)Bn*KEEPN*Dn);
}